// round 9
// baseline (speedup 1.0000x reference)
#include <cuda_runtime.h>

#define BB    8
#define NN    2048
#define NPTS  (BB*NN)        // 16384
#define CC    512
#define CIN   128
#define HH    96
#define WIW   96
#define IMG_ELEMS (BB*HH*WIW*CIN)   // 9437184

#define L0OFF (NPTS*CC)              // 8388608
#define L1OFF (L0OFF + NPTS*8)       // 8519680
#define L2OFF (L1OFF + NPTS*16)      // 8781824

// -------- scratch (static device allocation; no cudaMalloc allowed) --------
__device__ float g_TI [IMG_ELEMS];   // I  transposed to (b,x,y,c)
__device__ float g_TIT[IMG_ELEMS];   // IT transposed
__device__ float g_TJX[IMG_ELEMS];   // (IX - 0.5*I) transposed
__device__ float g_TJY[IMG_ELEMS];   // (IY - 0.5*I) transposed
__device__ float g_mask[NPTS*64];    // softmax mask, [pt][s*8+g]
__device__ float g_Z[NPTS*8*CIN];    // Z[pt][g][k]

// ============================================================================
// K0: transpose (B,Cin,H,W) -> (B,H,W,Cin) with fused JX/JY
// ============================================================================
__global__ void k0_transpose(const float* __restrict__ I, const float* __restrict__ IX,
                             const float* __restrict__ IY, const float* __restrict__ IT) {
    __shared__ float tI[32][33], tIX[32][33], tIY[32][33], tIT[32][33];
    int ct = blockIdx.x / 3, yt = blockIdx.x % 3;
    int xx = blockIdx.y, b = blockIdx.z;
    int tx = threadIdx.x, ty = threadIdx.y;
    #pragma unroll
    for (int rr = ty; rr < 32; rr += 8) {
        int c = ct*32 + rr;
        int y = yt*32 + tx;
        int src = ((b*CIN + c)*HH + xx)*WIW + y;
        tI [rr][tx] = I [src];
        tIX[rr][tx] = IX[src];
        tIY[rr][tx] = IY[src];
        tIT[rr][tx] = IT[src];
    }
    __syncthreads();
    #pragma unroll
    for (int rr = ty; rr < 32; rr += 8) {
        int c = ct*32 + tx;
        int y = yt*32 + rr;
        int dst = ((b*HH + xx)*WIW + y)*CIN + c;
        float vi = tI[tx][rr];
        g_TI [dst] = vi;
        g_TIT[dst] = tIT[tx][rr];
        g_TJX[dst] = tIX[tx][rr] - 0.5f*vi;
        g_TJY[dst] = tIY[tx][rr] - 0.5f*vi;
    }
}

// ============================================================================
// K1: fused (ratios | mask) logits + rect splits + softmax mask
//     ratio logits in fp64 (coordinate accuracy is amplified by ~1/area in K2)
// ============================================================================
#define K1_PTS 16
__global__ void k1_logits_rects(const float* __restrict__ x, const float* __restrict__ r,
                                const float* __restrict__ Wr, const float* __restrict__ br,
                                const float* __restrict__ Wm, const float* __restrict__ bm,
                                float* __restrict__ out) {
    __shared__ float xs[K1_PTS][516];   // padded
    __shared__ float lg[K1_PTS][72];
    __shared__ float rects[K1_PTS][56]; // [0,8)=L0, [8,24)=L1, [24,56)=L2
    int tid = threadIdx.x;
    int p0  = blockIdx.x * K1_PTS;

    for (int i = tid; i < K1_PTS*CC; i += 256) {
        int p = i >> 9, k = i & 511;
        xs[p][k] = x[(p0+p)*CC + k];
    }
    __syncthreads();

    // mask logits: fp32 with 4-way split accumulation (error ~1e-7 rel)
    for (int t = tid; t < K1_PTS*64; t += 256) {
        int p = t >> 6, jj = t & 63;
        float a0=0.f, a1=0.f, a2=0.f, a3=0.f;
        #pragma unroll 4
        for (int k = 0; k < CC; k += 4) {
            a0 += xs[p][k+0] * Wm[(k+0)*64 + jj];
            a1 += xs[p][k+1] * Wm[(k+1)*64 + jj];
            a2 += xs[p][k+2] * Wm[(k+2)*64 + jj];
            a3 += xs[p][k+3] * Wm[(k+3)*64 + jj];
        }
        lg[p][7 + jj] = (a0+a1) + (a2+a3);
    }

    // ratio logits: fp64 accumulation (coordinates feed 1/area amplification)
    if (tid < K1_PTS*7) {
        int p = tid / 7, j = tid % 7;
        double a0 = 0.0, a1 = 0.0;
        #pragma unroll 4
        for (int k = 0; k < CC; k += 2) {
            a0 += (double)xs[p][k+0] * (double)Wr[(k+0)*7 + j];
            a1 += (double)xs[p][k+1] * (double)Wr[(k+1)*7 + j];
        }
        lg[p][j] = (float)(a0 + a1);
    }
    __syncthreads();

    // rect splits: one thread per point (fp32, matching reference formula)
    if (tid < K1_PTS) {
        int gp = p0 + tid;
        float rat[7];
        #pragma unroll
        for (int i = 0; i < 7; i++)
            rat[i] = 1.f / (1.f + expf(-(lg[tid][i] + br[i])));
        float R0[4];
        #pragma unroll
        for (int i = 0; i < 4; i++) R0[i] = r[gp*4 + i];

        float A[2][4], Bv[4][4], Cv[8][4];
        { // level 0, dim 0: mid between p0,p2
            float mid = R0[0]*(1.f-rat[0]) + R0[2]*rat[0];
            A[0][0]=R0[0]; A[0][1]=R0[1]; A[0][2]=mid;   A[0][3]=R0[3];
            A[1][0]=mid;   A[1][1]=R0[1]; A[1][2]=R0[2]; A[1][3]=R0[3];
        }
        #pragma unroll
        for (int k = 0; k < 2; k++) { // level 1, dim 1
            float rt  = rat[1+k];
            float mid = A[k][1]*(1.f-rt) + A[k][3]*rt;
            Bv[k][0]=A[k][0];   Bv[k][1]=A[k][1]; Bv[k][2]=A[k][2];   Bv[k][3]=mid;
            Bv[2+k][0]=A[k][0]; Bv[2+k][1]=mid;   Bv[2+k][2]=A[k][2]; Bv[2+k][3]=A[k][3];
        }
        #pragma unroll
        for (int k = 0; k < 4; k++) { // level 2, dim 0
            float rt  = rat[3+k];
            float mid = Bv[k][0]*(1.f-rt) + Bv[k][2]*rt;
            Cv[k][0]=Bv[k][0]; Cv[k][1]=Bv[k][1]; Cv[k][2]=mid;      Cv[k][3]=Bv[k][3];
            Cv[4+k][0]=mid;    Cv[4+k][1]=Bv[k][1]; Cv[4+k][2]=Bv[k][2]; Cv[4+k][3]=Bv[k][3];
        }
        #pragma unroll
        for (int i = 0; i < 8;  i++) rects[tid][i]      = A[i>>2][i&3];
        #pragma unroll
        for (int i = 0; i < 16; i++) rects[tid][8+i]    = Bv[i>>2][i&3];
        #pragma unroll
        for (int i = 0; i < 32; i++) rects[tid][24+i]   = Cv[i>>2][i&3];
    }
    __syncthreads();

    // softmax over rects per (point, group) — accurate expf (errors here are
    // multiplied by S values that can be ~1e3-1e4 on tiny-area rects)
    if (tid < K1_PTS*8) {
        int p = tid >> 3, g = tid & 7;
        float m[8], mx = -1e30f;
        #pragma unroll
        for (int s = 0; s < 8; s++) { m[s] = lg[p][7 + s*8 + g] + bm[s*8 + g]; mx = fmaxf(mx, m[s]); }
        float sum = 0.f;
        #pragma unroll
        for (int s = 0; s < 8; s++) { m[s] = expf(m[s]-mx); sum += m[s]; }
        float inv = 1.f / sum;
        #pragma unroll
        for (int s = 0; s < 8; s++) g_mask[(p0+p)*64 + s*8 + g] = m[s]*inv;
    }

    // coalesced rect-output writes
    for (int i = tid; i < K1_PTS*8;  i += 256) out[L0OFF + p0*8  + i] = rects[i>>3][i&7];
    for (int i = tid; i < K1_PTS*16; i += 256) out[L1OFF + p0*16 + i] = rects[i>>4][8  + (i&15)];
    for (int i = tid; i < K1_PTS*32; i += 256) out[L2OFF + p0*32 + i] = rects[i>>5][24 + (i&31)];
}

// ============================================================================
// K2: integral-image sampling + mask-weighted combine -> Z
// ============================================================================
__device__ __forceinline__ float tl_eval(float px, float py, int basec) {
    float Xf = ceilf(px), Yf = ceilf(py);
    int X = (int)Xf, Y = (int)Yf;
    int Xm = max(X-1, 0), Ym = max(Y-1, 0);
    float dx = Xf - px, dy = Yf - py;
    float wx1 = 0.5f*dx*dx, wx2 = dx - wx1;
    float wy1 = 0.5f*dy*dy, wy2 = dy - wy1;
    int oXY   = basec + (X *WIW + Y )*CIN;
    int oXYm  = basec + (X *WIW + Ym)*CIN;
    int oXmY  = basec + (Xm*WIW + Y )*CIN;
    int oXmYm = basec + (Xm*WIW + Ym)*CIN;
    int o0Y   = basec + Y *CIN;
    int o0Ym  = basec + Ym*CIN;
    int oX0   = basec + X *WIW*CIN;
    int oXm0  = basec + Xm*WIW*CIN;
    float v = g_TIT[oXY];
    v -= wy1*g_TJX[oXYm] + wy2*g_TJX[oXY];
    v += 0.5f*(wy1*g_TI[o0Ym] + wy2*g_TI[o0Y]);
    v -= wx1*g_TJY[oXmY] + wx2*g_TJY[oXY];
    v += 0.5f*(wx1*g_TI[oXm0] + wx2*g_TI[oX0]);
    v += wx1*(wy1*g_TI[oXmYm] + wy2*g_TI[oXmY])
       + wx2*(wy1*g_TI[oXYm]  + wy2*g_TI[oXY]);
    return v;
}

__global__ void k2_sample(const float* __restrict__ out) {
    __shared__ float rr[32];
    __shared__ float msk[64];
    int pt  = blockIdx.x;
    int tid = threadIdx.x;                       // = channel
    if (tid < 32)       rr[tid]      = out[L2OFF + pt*32 + tid];
    else if (tid < 96)  msk[tid-32]  = g_mask[pt*64 + (tid-32)];
    __syncthreads();
    int b = pt >> 11;
    int basec = b*HH*WIW*CIN + tid;
    float zacc[8] = {0,0,0,0,0,0,0,0};
    #pragma unroll 1
    for (int s = 0; s < 8; s++) {
        float x1 = rr[s*4+0]*95.f, y1 = rr[s*4+1]*95.f;
        float x2 = rr[s*4+2]*95.f, y2 = rr[s*4+3]*95.f;
        float acc = tl_eval(x2,y2,basec) - tl_eval(x1,y2,basec)
                  - tl_eval(x2,y1,basec) + tl_eval(x1,y1,basec);
        float area = fabsf((x1-x2)*(y1-y2)) + 1e-9f;
        float Sv = acc / area;
        #pragma unroll
        for (int g = 0; g < 8; g++) zacc[g] += msk[s*8+g]*Sv;
    }
    #pragma unroll
    for (int g = 0; g < 8; g++)
        g_Z[(pt*8 + g)*CIN + tid] = zacc[g];
}

// ============================================================================
// K3: per-group GEMM  y_pre[p, g*64+c'] = Z[p,g,:] @ W_samp[:, g*64+c'] + b
// ============================================================================
__global__ void k3_gemm(const float* __restrict__ Wsamp, const float* __restrict__ bsamp,
                        float* __restrict__ out) {
    __shared__ float Zs[64][65];
    __shared__ float Wt[64][68];
    int p0  = blockIdx.x * 64;
    int g   = blockIdx.y;
    int tid = threadIdx.x;
    int tx  = tid & 15, ty = tid >> 4;
    float acc[4][4] = {};
    for (int kb = 0; kb < CIN; kb += 64) {
        __syncthreads();
        for (int i = tid; i < 4096; i += 256) {
            int p = i >> 6, kk = i & 63;
            Zs[p][kk] = g_Z[((p0+p)*8 + g)*CIN + kb + kk];
        }
        for (int i = tid; i < 4096; i += 256) {
            int kk = i >> 6, cc = i & 63;
            Wt[kk][cc] = Wsamp[(kb+kk)*CC + g*64 + cc];
        }
        __syncthreads();
        #pragma unroll 8
        for (int kk = 0; kk < 64; kk++) {
            float a0 = Zs[ty*4+0][kk], a1 = Zs[ty*4+1][kk];
            float a2 = Zs[ty*4+2][kk], a3 = Zs[ty*4+3][kk];
            float4 bv = *(const float4*)&Wt[kk][tx*4];
            acc[0][0] += a0*bv.x; acc[0][1] += a0*bv.y; acc[0][2] += a0*bv.z; acc[0][3] += a0*bv.w;
            acc[1][0] += a1*bv.x; acc[1][1] += a1*bv.y; acc[1][2] += a1*bv.z; acc[1][3] += a1*bv.w;
            acc[2][0] += a2*bv.x; acc[2][1] += a2*bv.y; acc[2][2] += a2*bv.z; acc[2][3] += a2*bv.w;
            acc[3][0] += a3*bv.x; acc[3][1] += a3*bv.y; acc[3][2] += a3*bv.z; acc[3][3] += a3*bv.w;
        }
    }
    int c0 = g*64 + tx*4;
    float4 bb = *(const float4*)&bsamp[c0];
    #pragma unroll
    for (int i = 0; i < 4; i++) {
        int row = p0 + ty*4 + i;
        float4 o;
        o.x = acc[i][0] + bb.x; o.y = acc[i][1] + bb.y;
        o.z = acc[i][2] + bb.z; o.w = acc[i][3] + bb.w;
        *(float4*)&out[row*CC + c0] = o;
    }
}

// ============================================================================
// K4: LayerNorm + residual, in place. Two-pass variance (stable).
// ============================================================================
__global__ void k4_ln(const float* __restrict__ x, const float* __restrict__ lng,
                      const float* __restrict__ lnb, float* __restrict__ out) {
    __shared__ float red[4];
    int pt = blockIdx.x, tid = threadIdx.x;
    const float* yp = out + pt*CC;
    const float* xp = x   + pt*CC;
    float v[4];
    float s1 = 0.f;
    #pragma unroll
    for (int j = 0; j < 4; j++) {
        v[j] = yp[j*128 + tid];
        s1 += v[j];
    }
    #pragma unroll
    for (int o = 16; o; o >>= 1) s1 += __shfl_xor_sync(0xFFFFFFFFu, s1, o);
    if ((tid & 31) == 0) red[tid>>5] = s1;
    __syncthreads();
    float mu = (red[0]+red[1]+red[2]+red[3]) * (1.f/512.f);
    __syncthreads();

    float s2 = 0.f;
    #pragma unroll
    for (int j = 0; j < 4; j++) { float d = v[j]-mu; s2 += d*d; }
    #pragma unroll
    for (int o = 16; o; o >>= 1) s2 += __shfl_xor_sync(0xFFFFFFFFu, s2, o);
    if ((tid & 31) == 0) red[tid>>5] = s2;
    __syncthreads();
    float var = (red[0]+red[1]+red[2]+red[3]) * (1.f/512.f);
    float rs  = rsqrtf(var + 1e-5f);
    #pragma unroll
    for (int j = 0; j < 4; j++) {
        int c = j*128 + tid;
        out[pt*CC + c] = (v[j]-mu)*rs*lng[c] + lnb[c] + xp[c];
    }
}

// ============================================================================
extern "C" void kernel_launch(void* const* d_in, const int* in_sizes, int n_in,
                              void* d_out, int out_size) {
    const float* x  = (const float*)d_in[0];
    const float* r  = (const float*)d_in[1];
    const float* I  = (const float*)d_in[2];
    const float* IX = (const float*)d_in[3];
    const float* IY = (const float*)d_in[4];
    const float* IT = (const float*)d_in[5];
    const float* Wr = (const float*)d_in[6];
    const float* br = (const float*)d_in[7];
    const float* Wm = (const float*)d_in[8];
    const float* bm = (const float*)d_in[9];
    const float* Ws = (const float*)d_in[10];
    const float* bs = (const float*)d_in[11];
    const float* lg = (const float*)d_in[12];
    const float* lb = (const float*)d_in[13];
    float* out = (float*)d_out;

    k0_transpose<<<dim3(12, 96, 8), dim3(32, 8)>>>(I, IX, IY, IT);
    k1_logits_rects<<<NPTS/K1_PTS, 256>>>(x, r, Wr, br, Wm, bm, out);
    k2_sample<<<NPTS, 128>>>(out);
    k3_gemm<<<dim3(NPTS/64, 8), 256>>>(Ws, bs, out);
    k4_ln<<<NPTS, 128>>>(x, lg, lb, out);
}

// round 10
// speedup vs baseline: 1.5968x; 1.5968x over previous
#include <cuda_runtime.h>

#define BB    8
#define NN    2048
#define NPTS  (BB*NN)        // 16384
#define CC    512
#define CIN   128
#define HH    96
#define WIW   96
#define IMG_ELEMS (BB*HH*WIW*CIN)   // 9437184

#define L0OFF (NPTS*CC)              // 8388608
#define L1OFF (L0OFF + NPTS*8)       // 8519680
#define L2OFF (L1OFF + NPTS*16)      // 8781824

// -------- scratch (static device allocation; no cudaMalloc allowed) --------
__device__ float g_TI [IMG_ELEMS];   // I  transposed to (b,x,y,c)
__device__ float g_TIT[IMG_ELEMS];   // IT transposed
__device__ float g_TJX[IMG_ELEMS];   // (IX - 0.5*I) transposed
__device__ float g_TJY[IMG_ELEMS];   // (IY - 0.5*I) transposed
__device__ float g_mask[NPTS*64];    // softmax mask, [pt][s*8+g]
__device__ float g_Z[NPTS*8*CIN];    // Z[pt][g][k]

// ============================================================================
// K0: transpose (B,Cin,H,W) -> (B,H,W,Cin) with fused JX/JY
// ============================================================================
__global__ void k0_transpose(const float* __restrict__ I, const float* __restrict__ IX,
                             const float* __restrict__ IY, const float* __restrict__ IT) {
    __shared__ float tI[32][33], tIX[32][33], tIY[32][33], tIT[32][33];
    int ct = blockIdx.x / 3, yt = blockIdx.x % 3;
    int xx = blockIdx.y, b = blockIdx.z;
    int tx = threadIdx.x, ty = threadIdx.y;
    #pragma unroll
    for (int rr = ty; rr < 32; rr += 8) {
        int c = ct*32 + rr;
        int y = yt*32 + tx;
        int src = ((b*CIN + c)*HH + xx)*WIW + y;
        tI [rr][tx] = I [src];
        tIX[rr][tx] = IX[src];
        tIY[rr][tx] = IY[src];
        tIT[rr][tx] = IT[src];
    }
    __syncthreads();
    #pragma unroll
    for (int rr = ty; rr < 32; rr += 8) {
        int c = ct*32 + tx;
        int y = yt*32 + rr;
        int dst = ((b*HH + xx)*WIW + y)*CIN + c;
        float vi = tI[tx][rr];
        g_TI [dst] = vi;
        g_TIT[dst] = tIT[tx][rr];
        g_TJX[dst] = tIX[tx][rr] - 0.5f*vi;
        g_TJY[dst] = tIY[tx][rr] - 0.5f*vi;
    }
}

// ============================================================================
// K1: fused (ratios | mask) logits + rect splits + softmax mask
//     ratio logits: fp32 8-term pairwise chunks -> double accumulator
// ============================================================================
#define K1_PTS 16
__global__ void k1_logits_rects(const float* __restrict__ x, const float* __restrict__ r,
                                const float* __restrict__ Wr, const float* __restrict__ br,
                                const float* __restrict__ Wm, const float* __restrict__ bm,
                                float* __restrict__ out) {
    __shared__ float xs[K1_PTS][516];   // padded
    __shared__ float lg[K1_PTS][72];
    __shared__ float rects[K1_PTS][56]; // [0,8)=L0, [8,24)=L1, [24,56)=L2
    int tid = threadIdx.x;
    int p0  = blockIdx.x * K1_PTS;

    for (int i = tid; i < K1_PTS*CC; i += 256) {
        int p = i >> 9, k = i & 511;
        xs[p][k] = x[(p0+p)*CC + k];
    }
    __syncthreads();

    // mask logits: fp32 with 4-way split accumulation
    for (int t = tid; t < K1_PTS*64; t += 256) {
        int p = t >> 6, jj = t & 63;
        float a0=0.f, a1=0.f, a2=0.f, a3=0.f;
        #pragma unroll 4
        for (int k = 0; k < CC; k += 4) {
            a0 += xs[p][k+0] * Wm[(k+0)*64 + jj];
            a1 += xs[p][k+1] * Wm[(k+1)*64 + jj];
            a2 += xs[p][k+2] * Wm[(k+2)*64 + jj];
            a3 += xs[p][k+3] * Wm[(k+3)*64 + jj];
        }
        lg[p][7 + jj] = (a0+a1) + (a2+a3);
    }

    // ratio logits: pairwise fp32 chunks of 8, summed into double (64 DADD/dot)
    if (tid < K1_PTS*7) {
        int p = tid / 7, j = tid % 7;
        double acc = 0.0;
        #pragma unroll 4
        for (int kb = 0; kb < CC; kb += 16) {
            float s0 = ((xs[p][kb+0]*Wr[(kb+0)*7+j] + xs[p][kb+1]*Wr[(kb+1)*7+j])
                      + (xs[p][kb+2]*Wr[(kb+2)*7+j] + xs[p][kb+3]*Wr[(kb+3)*7+j]))
                     + ((xs[p][kb+4]*Wr[(kb+4)*7+j] + xs[p][kb+5]*Wr[(kb+5)*7+j])
                      + (xs[p][kb+6]*Wr[(kb+6)*7+j] + xs[p][kb+7]*Wr[(kb+7)*7+j]));
            float s1 = ((xs[p][kb+8]*Wr[(kb+8)*7+j] + xs[p][kb+9]*Wr[(kb+9)*7+j])
                      + (xs[p][kb+10]*Wr[(kb+10)*7+j] + xs[p][kb+11]*Wr[(kb+11)*7+j]))
                     + ((xs[p][kb+12]*Wr[(kb+12)*7+j] + xs[p][kb+13]*Wr[(kb+13)*7+j])
                      + (xs[p][kb+14]*Wr[(kb+14)*7+j] + xs[p][kb+15]*Wr[(kb+15)*7+j]));
            acc += (double)s0 + (double)s1;
        }
        lg[p][j] = (float)acc;
    }
    __syncthreads();

    // rect splits: one thread per point (fp32, matching reference formula)
    if (tid < K1_PTS) {
        int gp = p0 + tid;
        float rat[7];
        #pragma unroll
        for (int i = 0; i < 7; i++)
            rat[i] = 1.f / (1.f + expf(-(lg[tid][i] + br[i])));
        float R0[4];
        #pragma unroll
        for (int i = 0; i < 4; i++) R0[i] = r[gp*4 + i];

        float A[2][4], Bv[4][4], Cv[8][4];
        { // level 0, dim 0: mid between p0,p2
            float mid = R0[0]*(1.f-rat[0]) + R0[2]*rat[0];
            A[0][0]=R0[0]; A[0][1]=R0[1]; A[0][2]=mid;   A[0][3]=R0[3];
            A[1][0]=mid;   A[1][1]=R0[1]; A[1][2]=R0[2]; A[1][3]=R0[3];
        }
        #pragma unroll
        for (int k = 0; k < 2; k++) { // level 1, dim 1
            float rt  = rat[1+k];
            float mid = A[k][1]*(1.f-rt) + A[k][3]*rt;
            Bv[k][0]=A[k][0];   Bv[k][1]=A[k][1]; Bv[k][2]=A[k][2];   Bv[k][3]=mid;
            Bv[2+k][0]=A[k][0]; Bv[2+k][1]=mid;   Bv[2+k][2]=A[k][2]; Bv[2+k][3]=A[k][3];
        }
        #pragma unroll
        for (int k = 0; k < 4; k++) { // level 2, dim 0
            float rt  = rat[3+k];
            float mid = Bv[k][0]*(1.f-rt) + Bv[k][2]*rt;
            Cv[k][0]=Bv[k][0]; Cv[k][1]=Bv[k][1]; Cv[k][2]=mid;      Cv[k][3]=Bv[k][3];
            Cv[4+k][0]=mid;    Cv[4+k][1]=Bv[k][1]; Cv[4+k][2]=Bv[k][2]; Cv[4+k][3]=Bv[k][3];
        }
        #pragma unroll
        for (int i = 0; i < 8;  i++) rects[tid][i]      = A[i>>2][i&3];
        #pragma unroll
        for (int i = 0; i < 16; i++) rects[tid][8+i]    = Bv[i>>2][i&3];
        #pragma unroll
        for (int i = 0; i < 32; i++) rects[tid][24+i]   = Cv[i>>2][i&3];
    }
    __syncthreads();

    // softmax over rects per (point, group)
    if (tid < K1_PTS*8) {
        int p = tid >> 3, g = tid & 7;
        float m[8], mx = -1e30f;
        #pragma unroll
        for (int s = 0; s < 8; s++) { m[s] = lg[p][7 + s*8 + g] + bm[s*8 + g]; mx = fmaxf(mx, m[s]); }
        float sum = 0.f;
        #pragma unroll
        for (int s = 0; s < 8; s++) { m[s] = expf(m[s]-mx); sum += m[s]; }
        float inv = 1.f / sum;
        #pragma unroll
        for (int s = 0; s < 8; s++) g_mask[(p0+p)*64 + s*8 + g] = m[s]*inv;
    }

    // coalesced rect-output writes
    for (int i = tid; i < K1_PTS*8;  i += 256) out[L0OFF + p0*8  + i] = rects[i>>3][i&7];
    for (int i = tid; i < K1_PTS*16; i += 256) out[L1OFF + p0*16 + i] = rects[i>>4][8  + (i&15)];
    for (int i = tid; i < K1_PTS*32; i += 256) out[L2OFF + p0*32 + i] = rects[i>>5][24 + (i&31)];
}

// ============================================================================
// K2: integral-image sampling with 18-unique-corner dedup + edge-term hoist
//     8 rects per point tile the parent rect: 7 unique x coords, 4 unique y.
//     loads/point/channel: 18*9 + 8 + 14 = 184 (vs naive 32*13 = 416)
// ============================================================================
__global__ void __launch_bounds__(128) k2_sample(const float* __restrict__ out) {
    __shared__ float rrs[32];     // scaled rect coords
    __shared__ float msk[64];
    __shared__ int   sxX[7], sxXm[7], syY[4], syYm[4];
    __shared__ float swx1[7], swx2[7], swy1[4], swy2[4];
    int pt  = blockIdx.x;
    int tid = threadIdx.x;                       // = channel
    if (tid < 32)       rrs[tid]     = out[L2OFF + pt*32 + tid] * 95.f;
    else if (tid < 96)  msk[tid-32]  = g_mask[pt*64 + (tid-32)];
    __syncthreads();
    // unique coords: x: {x1, m0, x2, mx0..mx3}  y: {y1, m1a, m1b, y2}
    if (tid < 7) {
        const int xsrc[7] = {0, 4, 22, 2, 6, 10, 14};
        float px = rrs[xsrc[tid]];
        float Xf = ceilf(px);
        int X = (int)Xf, Xm = max(X-1, 0);
        float dx = Xf - px;
        float w1 = 0.5f*dx*dx;
        swx1[tid] = w1; swx2[tid] = dx - w1;
        sxX[tid]  = X *(WIW*CIN);
        sxXm[tid] = Xm*(WIW*CIN);
    } else if (tid >= 8 && tid < 12) {
        const int ysrc[4] = {1, 3, 7, 11};
        int t = tid - 8;
        float py = rrs[ysrc[t]];
        float Yf = ceilf(py);
        int Y = (int)Yf, Ym = max(Y-1, 0);
        float dy = Yf - py;
        float w1 = 0.5f*dy*dy;
        swy1[t] = w1; swy2[t] = dy - w1;
        syY[t]  = Y *CIN;
        syYm[t] = Ym*CIN;
    }
    __syncthreads();
    int b = pt >> 11;
    int basec = b*HH*WIW*CIN + tid;

    // edge terms: functions of one coordinate only
    float ey[4], ex[7];
    #pragma unroll
    for (int yi = 0; yi < 4; yi++)
        ey[yi] = 0.5f*(swy1[yi]*g_TI[basec + syYm[yi]] + swy2[yi]*g_TI[basec + syY[yi]]);
    #pragma unroll
    for (int xi = 0; xi < 7; xi++)
        ex[xi] = 0.5f*(swx1[xi]*g_TI[basec + sxXm[xi]] + swx2[xi]*g_TI[basec + sxX[xi]]);

    // 18 unique corner evaluations
    const int CXI[18] = {0,0,1,1,3,3, 1,2,2,4,4, 0,1,5,5, 2,6,6};
    const int CYI[18] = {0,1,0,1,0,1, 2,0,2,0,2, 3,3,1,3, 3,2,3};
    float c[18];
    #pragma unroll
    for (int i = 0; i < 18; i++) {
        int xi = CXI[i], yi = CYI[i];
        int oX = sxX[xi], oXm = sxXm[xi], oY = syY[yi], oYm = syYm[yi];
        float wx1 = swx1[xi], wx2 = swx2[xi], wy1 = swy1[yi], wy2 = swy2[yi];
        int aXY   = basec + oX  + oY;
        int aXYm  = basec + oX  + oYm;
        int aXmY  = basec + oXm + oY;
        int aXmYm = basec + oXm + oYm;
        float v = g_TIT[aXY];
        v -= wy1*g_TJX[aXYm] + wy2*g_TJX[aXY];
        v -= wx1*g_TJY[aXmY] + wx2*g_TJY[aXY];
        v += ey[yi] + ex[xi];
        v += wx1*(wy1*g_TI[aXmYm] + wy2*g_TI[aXmY])
           + wx2*(wy1*g_TI[aXYm]  + wy2*g_TI[aXY]);
        c[i] = v;
    }

    // rect combines: S_s = c[A]-c[B]-c[C]+c[D], then mask-weighted Z
    const int RA[8] = {5,10,14,17, 3, 8,12,15};
    const int RB[8] = {1, 6,11,12, 5,10,14,17};
    const int RC[8] = {4, 9,13,16, 2, 7, 3, 8};
    const int RD[8] = {0, 2, 1, 6, 4, 9,13,16};
    float zacc[8] = {0,0,0,0,0,0,0,0};
    #pragma unroll
    for (int s = 0; s < 8; s++) {
        float x1 = rrs[s*4+0], y1 = rrs[s*4+1], x2 = rrs[s*4+2], y2 = rrs[s*4+3];
        float area = fabsf((x1-x2)*(y1-y2)) + 1e-9f;
        float Sv = (((c[RA[s]] - c[RB[s]]) - c[RC[s]]) + c[RD[s]]) / area;
        #pragma unroll
        for (int g = 0; g < 8; g++) zacc[g] += msk[s*8+g]*Sv;
    }
    #pragma unroll
    for (int g = 0; g < 8; g++)
        g_Z[(pt*8 + g)*CIN + tid] = zacc[g];
}

// ============================================================================
// K3: per-group GEMM  y_pre[p, g*64+c'] = Z[p,g,:] @ W_samp[:, g*64+c'] + b
//     Zs transposed to [kk][p] so A-fragment is one LDS.128
// ============================================================================
__global__ void k3_gemm(const float* __restrict__ Wsamp, const float* __restrict__ bsamp,
                        float* __restrict__ out) {
    __shared__ float Zs[64][68];
    __shared__ float Wt[64][68];
    int p0  = blockIdx.x * 64;
    int g   = blockIdx.y;
    int tid = threadIdx.x;
    int tx  = tid & 15, ty = tid >> 4;
    float acc[4][4] = {};
    for (int kb = 0; kb < CIN; kb += 64) {
        __syncthreads();
        for (int i = tid; i < 4096; i += 256) {
            int p = i >> 6, kk = i & 63;
            Zs[kk][p] = g_Z[((p0+p)*8 + g)*CIN + kb + kk];
        }
        for (int i = tid; i < 4096; i += 256) {
            int kk = i >> 6, cc = i & 63;
            Wt[kk][cc] = Wsamp[(kb+kk)*CC + g*64 + cc];
        }
        __syncthreads();
        #pragma unroll 8
        for (int kk = 0; kk < 64; kk++) {
            float4 av = *(const float4*)&Zs[kk][ty*4];
            float4 bv = *(const float4*)&Wt[kk][tx*4];
            acc[0][0] += av.x*bv.x; acc[0][1] += av.x*bv.y; acc[0][2] += av.x*bv.z; acc[0][3] += av.x*bv.w;
            acc[1][0] += av.y*bv.x; acc[1][1] += av.y*bv.y; acc[1][2] += av.y*bv.z; acc[1][3] += av.y*bv.w;
            acc[2][0] += av.z*bv.x; acc[2][1] += av.z*bv.y; acc[2][2] += av.z*bv.z; acc[2][3] += av.z*bv.w;
            acc[3][0] += av.w*bv.x; acc[3][1] += av.w*bv.y; acc[3][2] += av.w*bv.z; acc[3][3] += av.w*bv.w;
        }
    }
    int c0 = g*64 + tx*4;
    float4 bb = *(const float4*)&bsamp[c0];
    #pragma unroll
    for (int i = 0; i < 4; i++) {
        int row = p0 + ty*4 + i;
        float4 o;
        o.x = acc[i][0] + bb.x; o.y = acc[i][1] + bb.y;
        o.z = acc[i][2] + bb.z; o.w = acc[i][3] + bb.w;
        *(float4*)&out[row*CC + c0] = o;
    }
}

// ============================================================================
// K4: LayerNorm + residual, in place. Two-pass variance (stable).
// ============================================================================
__global__ void k4_ln(const float* __restrict__ x, const float* __restrict__ lng,
                      const float* __restrict__ lnb, float* __restrict__ out) {
    __shared__ float red[4];
    int pt = blockIdx.x, tid = threadIdx.x;
    const float* yp = out + pt*CC;
    const float* xp = x   + pt*CC;
    float v[4];
    float s1 = 0.f;
    #pragma unroll
    for (int j = 0; j < 4; j++) {
        v[j] = yp[j*128 + tid];
        s1 += v[j];
    }
    #pragma unroll
    for (int o = 16; o; o >>= 1) s1 += __shfl_xor_sync(0xFFFFFFFFu, s1, o);
    if ((tid & 31) == 0) red[tid>>5] = s1;
    __syncthreads();
    float mu = (red[0]+red[1]+red[2]+red[3]) * (1.f/512.f);
    __syncthreads();

    float s2 = 0.f;
    #pragma unroll
    for (int j = 0; j < 4; j++) { float d = v[j]-mu; s2 += d*d; }
    #pragma unroll
    for (int o = 16; o; o >>= 1) s2 += __shfl_xor_sync(0xFFFFFFFFu, s2, o);
    if ((tid & 31) == 0) red[tid>>5] = s2;
    __syncthreads();
    float var = (red[0]+red[1]+red[2]+red[3]) * (1.f/512.f);
    float rs  = rsqrtf(var + 1e-5f);
    #pragma unroll
    for (int j = 0; j < 4; j++) {
        int c = j*128 + tid;
        out[pt*CC + c] = (v[j]-mu)*rs*lng[c] + lnb[c] + xp[c];
    }
}

// ============================================================================
extern "C" void kernel_launch(void* const* d_in, const int* in_sizes, int n_in,
                              void* d_out, int out_size) {
    const float* x  = (const float*)d_in[0];
    const float* r  = (const float*)d_in[1];
    const float* I  = (const float*)d_in[2];
    const float* IX = (const float*)d_in[3];
    const float* IY = (const float*)d_in[4];
    const float* IT = (const float*)d_in[5];
    const float* Wr = (const float*)d_in[6];
    const float* br = (const float*)d_in[7];
    const float* Wm = (const float*)d_in[8];
    const float* bm = (const float*)d_in[9];
    const float* Ws = (const float*)d_in[10];
    const float* bs = (const float*)d_in[11];
    const float* lg = (const float*)d_in[12];
    const float* lb = (const float*)d_in[13];
    float* out = (float*)d_out;

    k0_transpose<<<dim3(12, 96, 8), dim3(32, 8)>>>(I, IX, IY, IT);
    k1_logits_rects<<<NPTS/K1_PTS, 256>>>(x, r, Wr, br, Wm, bm, out);
    k2_sample<<<NPTS, 128>>>(out);
    k3_gemm<<<dim3(NPTS/64, 8), 256>>>(Ws, bs, out);
    k4_ln<<<NPTS, 128>>>(x, lg, lb, out);
}

// round 12
// speedup vs baseline: 1.8548x; 1.1616x over previous
#include <cuda_runtime.h>

#define BB    8
#define NN    2048
#define NPTS  (BB*NN)        // 16384
#define CC    512
#define CIN   128
#define HH    96
#define WIW   96
#define IMG_ELEMS (BB*HH*WIW*CIN)   // 9437184

#define L0OFF (NPTS*CC)              // 8388608
#define L1OFF (L0OFF + NPTS*8)       // 8519680
#define L2OFF (L1OFF + NPTS*16)      // 8781824

// -------- scratch (static device allocation; no cudaMalloc allowed) --------
__device__ __align__(16) float g_TI [IMG_ELEMS];   // I  transposed to (b,x,y,c)
__device__ __align__(16) float g_TIT[IMG_ELEMS];   // IT transposed
__device__ __align__(16) float g_TJX[IMG_ELEMS];   // (IX - 0.5*I) transposed
__device__ __align__(16) float g_TJY[IMG_ELEMS];   // (IY - 0.5*I) transposed
__device__ __align__(16) float g_mask[NPTS*64];    // softmax mask, [pt][s*8+g]
__device__ __align__(16) float g_Z[NPTS*8*CIN];    // Z[pt][g][k]

// ============================================================================
// K0: transpose (B,Cin,H,W) -> (B,H,W,Cin) with fused JX/JY
// ============================================================================
__global__ void k0_transpose(const float* __restrict__ I, const float* __restrict__ IX,
                             const float* __restrict__ IY, const float* __restrict__ IT) {
    __shared__ float tI[32][33], tIX[32][33], tIY[32][33], tIT[32][33];
    int ct = blockIdx.x / 3, yt = blockIdx.x % 3;
    int xx = blockIdx.y, b = blockIdx.z;
    int tx = threadIdx.x, ty = threadIdx.y;
    #pragma unroll
    for (int rr = ty; rr < 32; rr += 8) {
        int c = ct*32 + rr;
        int y = yt*32 + tx;
        int src = ((b*CIN + c)*HH + xx)*WIW + y;
        tI [rr][tx] = I [src];
        tIX[rr][tx] = IX[src];
        tIY[rr][tx] = IY[src];
        tIT[rr][tx] = IT[src];
    }
    __syncthreads();
    #pragma unroll
    for (int rr = ty; rr < 32; rr += 8) {
        int c = ct*32 + tx;
        int y = yt*32 + rr;
        int dst = ((b*HH + xx)*WIW + y)*CIN + c;
        float vi = tI[tx][rr];
        g_TI [dst] = vi;
        g_TIT[dst] = tIT[tx][rr];
        g_TJX[dst] = tIX[tx][rr] - 0.5f*vi;
        g_TJY[dst] = tIY[tx][rr] - 0.5f*vi;
    }
}

// ============================================================================
// K1: fused (ratios | mask) logits + rect splits + softmax mask
// ============================================================================
#define K1_PTS 16
__global__ void k1_logits_rects(const float* __restrict__ x, const float* __restrict__ r,
                                const float* __restrict__ Wr, const float* __restrict__ br,
                                const float* __restrict__ Wm, const float* __restrict__ bm,
                                float* __restrict__ out) {
    __shared__ float xs[K1_PTS][516];   // padded (516 % 4 == 0 keeps float4 alignment)
    __shared__ float lg[K1_PTS][72];
    __shared__ float rects[K1_PTS][56]; // [0,8)=L0, [8,24)=L1, [24,56)=L2
    int tid = threadIdx.x;
    int p0  = blockIdx.x * K1_PTS;

    for (int i = tid; i < K1_PTS*CC; i += 256) {
        int p = i >> 9, k = i & 511;
        xs[p][k] = x[(p0+p)*CC + k];
    }
    __syncthreads();

    // mask logits: thread = (point, 4 cols); float4 loads; split-4 accumulation
    {
        int p = tid >> 4, q = tid & 15;     // q*4 = first col
        float4 a0 = {0,0,0,0}, a1 = {0,0,0,0}, a2 = {0,0,0,0}, a3 = {0,0,0,0};
        #pragma unroll 4
        for (int k = 0; k < CC; k += 4) {
            float4 xv = *(const float4*)&xs[p][k];
            float4 w0 = *(const float4*)&Wm[(k+0)*64 + q*4];
            float4 w1 = *(const float4*)&Wm[(k+1)*64 + q*4];
            float4 w2 = *(const float4*)&Wm[(k+2)*64 + q*4];
            float4 w3 = *(const float4*)&Wm[(k+3)*64 + q*4];
            a0.x += xv.x*w0.x; a0.y += xv.x*w0.y; a0.z += xv.x*w0.z; a0.w += xv.x*w0.w;
            a1.x += xv.y*w1.x; a1.y += xv.y*w1.y; a1.z += xv.y*w1.z; a1.w += xv.y*w1.w;
            a2.x += xv.z*w2.x; a2.y += xv.z*w2.y; a2.z += xv.z*w2.z; a2.w += xv.z*w2.w;
            a3.x += xv.w*w3.x; a3.y += xv.w*w3.y; a3.z += xv.w*w3.z; a3.w += xv.w*w3.w;
        }
        lg[p][7 + q*4 + 0] = (a0.x+a1.x) + (a2.x+a3.x);
        lg[p][7 + q*4 + 1] = (a0.y+a1.y) + (a2.y+a3.y);
        lg[p][7 + q*4 + 2] = (a0.z+a1.z) + (a2.z+a3.z);
        lg[p][7 + q*4 + 3] = (a0.w+a1.w) + (a2.w+a3.w);
    }

    // ratio logits: pairwise fp32 chunks of 8, summed into double
    if (tid < K1_PTS*7) {
        int p = tid / 7, j = tid % 7;
        double acc = 0.0;
        #pragma unroll 4
        for (int kb = 0; kb < CC; kb += 16) {
            float s0 = ((xs[p][kb+0]*Wr[(kb+0)*7+j] + xs[p][kb+1]*Wr[(kb+1)*7+j])
                      + (xs[p][kb+2]*Wr[(kb+2)*7+j] + xs[p][kb+3]*Wr[(kb+3)*7+j]))
                     + ((xs[p][kb+4]*Wr[(kb+4)*7+j] + xs[p][kb+5]*Wr[(kb+5)*7+j])
                      + (xs[p][kb+6]*Wr[(kb+6)*7+j] + xs[p][kb+7]*Wr[(kb+7)*7+j]));
            float s1 = ((xs[p][kb+8]*Wr[(kb+8)*7+j] + xs[p][kb+9]*Wr[(kb+9)*7+j])
                      + (xs[p][kb+10]*Wr[(kb+10)*7+j] + xs[p][kb+11]*Wr[(kb+11)*7+j]))
                     + ((xs[p][kb+12]*Wr[(kb+12)*7+j] + xs[p][kb+13]*Wr[(kb+13)*7+j])
                      + (xs[p][kb+14]*Wr[(kb+14)*7+j] + xs[p][kb+15]*Wr[(kb+15)*7+j]));
            acc += (double)s0 + (double)s1;
        }
        lg[p][j] = (float)acc;
    }
    __syncthreads();

    // rect splits: one thread per point (fp32, matching reference formula)
    if (tid < K1_PTS) {
        int gp = p0 + tid;
        float rat[7];
        #pragma unroll
        for (int i = 0; i < 7; i++)
            rat[i] = 1.f / (1.f + expf(-(lg[tid][i] + br[i])));
        float R0[4];
        #pragma unroll
        for (int i = 0; i < 4; i++) R0[i] = r[gp*4 + i];

        float A[2][4], Bv[4][4], Cv[8][4];
        {
            float mid = R0[0]*(1.f-rat[0]) + R0[2]*rat[0];
            A[0][0]=R0[0]; A[0][1]=R0[1]; A[0][2]=mid;   A[0][3]=R0[3];
            A[1][0]=mid;   A[1][1]=R0[1]; A[1][2]=R0[2]; A[1][3]=R0[3];
        }
        #pragma unroll
        for (int k = 0; k < 2; k++) {
            float rt  = rat[1+k];
            float mid = A[k][1]*(1.f-rt) + A[k][3]*rt;
            Bv[k][0]=A[k][0];   Bv[k][1]=A[k][1]; Bv[k][2]=A[k][2];   Bv[k][3]=mid;
            Bv[2+k][0]=A[k][0]; Bv[2+k][1]=mid;   Bv[2+k][2]=A[k][2]; Bv[2+k][3]=A[k][3];
        }
        #pragma unroll
        for (int k = 0; k < 4; k++) {
            float rt  = rat[3+k];
            float mid = Bv[k][0]*(1.f-rt) + Bv[k][2]*rt;
            Cv[k][0]=Bv[k][0]; Cv[k][1]=Bv[k][1]; Cv[k][2]=mid;      Cv[k][3]=Bv[k][3];
            Cv[4+k][0]=mid;    Cv[4+k][1]=Bv[k][1]; Cv[4+k][2]=Bv[k][2]; Cv[4+k][3]=Bv[k][3];
        }
        #pragma unroll
        for (int i = 0; i < 8;  i++) rects[tid][i]      = A[i>>2][i&3];
        #pragma unroll
        for (int i = 0; i < 16; i++) rects[tid][8+i]    = Bv[i>>2][i&3];
        #pragma unroll
        for (int i = 0; i < 32; i++) rects[tid][24+i]   = Cv[i>>2][i&3];
    }
    __syncthreads();

    // softmax over rects per (point, group)
    if (tid < K1_PTS*8) {
        int p = tid >> 3, g = tid & 7;
        float m[8], mx = -1e30f;
        #pragma unroll
        for (int s = 0; s < 8; s++) { m[s] = lg[p][7 + s*8 + g] + bm[s*8 + g]; mx = fmaxf(mx, m[s]); }
        float sum = 0.f;
        #pragma unroll
        for (int s = 0; s < 8; s++) { m[s] = expf(m[s]-mx); sum += m[s]; }
        float inv = 1.f / sum;
        #pragma unroll
        for (int s = 0; s < 8; s++) g_mask[(p0+p)*64 + s*8 + g] = m[s]*inv;
    }

    for (int i = tid; i < K1_PTS*8;  i += 256) out[L0OFF + p0*8  + i] = rects[i>>3][i&7];
    for (int i = tid; i < K1_PTS*16; i += 256) out[L1OFF + p0*16 + i] = rects[i>>4][8  + (i&15)];
    for (int i = tid; i < K1_PTS*32; i += 256) out[L2OFF + p0*32 + i] = rects[i>>5][24 + (i&31)];
}

// ============================================================================
// K2: integral-image sampling, 18-corner dedup + edge hoist, float2 channels
//     2 points/block, 64 threads/point, each thread owns 2 channels
// ============================================================================
__device__ __forceinline__ float corner_eval(float tit, float jxm, float jx0,
                                             float jym, float jy0,
                                             float timm, float tim0, float ti0m, float ti00,
                                             float wx1, float wx2, float wy1, float wy2,
                                             float eyv, float exv) {
    float v = tit;
    v -= wy1*jxm + wy2*jx0;
    v -= wx1*jym + wx2*jy0;
    v += eyv + exv;
    v += wx1*(wy1*timm + wy2*tim0) + wx2*(wy1*ti0m + wy2*ti00);
    return v;
}

__global__ void __launch_bounds__(128) k2_sample(const float* __restrict__ out) {
    __shared__ float rrs[2][32];
    __shared__ float msk[2][64];
    __shared__ int   sxX[2][7], sxXm[2][7], syY[2][4], syYm[2][4];
    __shared__ float swx1[2][7], swx2[2][7], swy1[2][4], swy2[2][4];
    int tid  = threadIdx.x;
    int half = tid >> 6, l = tid & 63;
    int pt   = blockIdx.x*2 + half;
    if (l < 32) rrs[half][l] = out[L2OFF + pt*32 + l] * 95.f;
    msk[half][l] = g_mask[pt*64 + l];
    __syncthreads();
    if (l < 7) {
        const int xsrc[7] = {0, 4, 22, 2, 6, 10, 14};
        float px = rrs[half][xsrc[l]];
        float Xf = ceilf(px);
        int X = (int)Xf, Xm = max(X-1, 0);
        float dx = Xf - px;
        float w1 = 0.5f*dx*dx;
        swx1[half][l] = w1; swx2[half][l] = dx - w1;
        sxX[half][l]  = X *(WIW*64);     // float2 units
        sxXm[half][l] = Xm*(WIW*64);
    } else if (l >= 8 && l < 12) {
        const int ysrc[4] = {1, 3, 7, 11};
        int t = l - 8;
        float py = rrs[half][ysrc[t]];
        float Yf = ceilf(py);
        int Y = (int)Yf, Ym = max(Y-1, 0);
        float dy = Yf - py;
        float w1 = 0.5f*dy*dy;
        swy1[half][t] = w1; swy2[half][t] = dy - w1;
        syY[half][t]  = Y *64;           // float2 units
        syYm[half][t] = Ym*64;
    }
    __syncthreads();

    const float2* TI2  = (const float2*)g_TI;
    const float2* TIT2 = (const float2*)g_TIT;
    const float2* TJX2 = (const float2*)g_TJX;
    const float2* TJY2 = (const float2*)g_TJY;
    int b = pt >> 11;
    int base2 = b*(HH*WIW*64) + l;      // float2 units; channel pair = l

    // edge terms (float2)
    float2 ey[4], ex[7];
    #pragma unroll
    for (int yi = 0; yi < 4; yi++) {
        float2 tm = TI2[base2 + syYm[half][yi]];
        float2 t0 = TI2[base2 + syY [half][yi]];
        float w1 = swy1[half][yi], w2 = swy2[half][yi];
        ey[yi].x = 0.5f*(w1*tm.x + w2*t0.x);
        ey[yi].y = 0.5f*(w1*tm.y + w2*t0.y);
    }
    #pragma unroll
    for (int xi = 0; xi < 7; xi++) {
        float2 tm = TI2[base2 + sxXm[half][xi]];
        float2 t0 = TI2[base2 + sxX [half][xi]];
        float w1 = swx1[half][xi], w2 = swx2[half][xi];
        ex[xi].x = 0.5f*(w1*tm.x + w2*t0.x);
        ex[xi].y = 0.5f*(w1*tm.y + w2*t0.y);
    }

    // 18 unique corners
    const int CXI[18] = {0,0,1,1,3,3, 1,2,2,4,4, 0,1,5,5, 2,6,6};
    const int CYI[18] = {0,1,0,1,0,1, 2,0,2,0,2, 3,3,1,3, 3,2,3};
    float2 c[18];
    #pragma unroll
    for (int i = 0; i < 18; i++) {
        int xi = CXI[i], yi = CYI[i];
        int oX = sxX[half][xi], oXm = sxXm[half][xi];
        int oY = syY[half][yi], oYm = syYm[half][yi];
        float wx1 = swx1[half][xi], wx2 = swx2[half][xi];
        float wy1 = swy1[half][yi], wy2 = swy2[half][yi];
        int aXY   = base2 + oX  + oY;
        int aXYm  = base2 + oX  + oYm;
        int aXmY  = base2 + oXm + oY;
        int aXmYm = base2 + oXm + oYm;
        float2 tit  = TIT2[aXY];
        float2 jxm  = TJX2[aXYm], jx0 = TJX2[aXY];
        float2 jym  = TJY2[aXmY], jy0 = TJY2[aXY];
        float2 timm = TI2[aXmYm], tim0 = TI2[aXmY];
        float2 ti0m = TI2[aXYm],  ti00 = TI2[aXY];
        c[i].x = corner_eval(tit.x, jxm.x, jx0.x, jym.x, jy0.x,
                             timm.x, tim0.x, ti0m.x, ti00.x,
                             wx1, wx2, wy1, wy2, ey[yi].x, ex[xi].x);
        c[i].y = corner_eval(tit.y, jxm.y, jx0.y, jym.y, jy0.y,
                             timm.y, tim0.y, ti0m.y, ti00.y,
                             wx1, wx2, wy1, wy2, ey[yi].y, ex[xi].y);
    }

    // rect combines in exact reference order, then mask-weighted Z
    const int RA[8] = {5,10,14,17, 3, 8,12,15};
    const int RB[8] = {1, 6,11,12, 5,10,14,17};
    const int RC[8] = {4, 9,13,16, 2, 7, 3, 8};
    const int RD[8] = {0, 2, 1, 6, 4, 9,13,16};
    float2 zacc[8];
    #pragma unroll
    for (int g = 0; g < 8; g++) { zacc[g].x = 0.f; zacc[g].y = 0.f; }
    #pragma unroll
    for (int s = 0; s < 8; s++) {
        float x1 = rrs[half][s*4+0], y1 = rrs[half][s*4+1];
        float x2 = rrs[half][s*4+2], y2 = rrs[half][s*4+3];
        float inva = 1.f / (fabsf((x1-x2)*(y1-y2)) + 1e-9f);
        float Svx = (((c[RA[s]].x - c[RB[s]].x) - c[RC[s]].x) + c[RD[s]].x) * inva;
        float Svy = (((c[RA[s]].y - c[RB[s]].y) - c[RC[s]].y) + c[RD[s]].y) * inva;
        #pragma unroll
        for (int g = 0; g < 8; g++) {
            float m = msk[half][s*8+g];
            zacc[g].x += m*Svx;
            zacc[g].y += m*Svy;
        }
    }
    float2* gZ2 = (float2*)g_Z;
    #pragma unroll
    for (int g = 0; g < 8; g++)
        gZ2[(pt*8 + g)*64 + l] = zacc[g];
}

// ============================================================================
// K3: per-group GEMM, 128 pts x 64 cols per block, 8x8 per thread
//     Zs transposed [kk][p] (pad 132): 4x LDS.128 per 64 FFMA -> balanced
// ============================================================================
__global__ void __launch_bounds__(128) k3_gemm(const float* __restrict__ Wsamp,
                                               const float* __restrict__ bsamp,
                                               float* __restrict__ out) {
    __shared__ float Zs[64][132];
    __shared__ float Wt[64][68];
    int p0  = blockIdx.x * 128;
    int g   = blockIdx.y;
    int tid = threadIdx.x;
    int tx  = tid & 7, ty = tid >> 3;   // tx: 8 col-octets, ty: 16 row-octets
    float acc[8][8] = {};
    for (int kb = 0; kb < CIN; kb += 64) {
        __syncthreads();
        for (int i = tid; i < 8192; i += 128) {
            int p = i >> 6, kk = i & 63;
            Zs[kk][p] = g_Z[((p0+p)*8 + g)*CIN + kb + kk];
        }
        for (int i = tid; i < 4096; i += 128) {
            int kk = i >> 6, cc = i & 63;
            Wt[kk][cc] = Wsamp[(kb+kk)*CC + g*64 + cc];
        }
        __syncthreads();
        #pragma unroll 4
        for (int kk = 0; kk < 64; kk++) {
            float4 a0 = *(const float4*)&Zs[kk][ty*8];
            float4 a1 = *(const float4*)&Zs[kk][ty*8+4];
            float4 b0 = *(const float4*)&Wt[kk][tx*8];
            float4 b1 = *(const float4*)&Wt[kk][tx*8+4];
            float av[8] = {a0.x,a0.y,a0.z,a0.w,a1.x,a1.y,a1.z,a1.w};
            float bv[8] = {b0.x,b0.y,b0.z,b0.w,b1.x,b1.y,b1.z,b1.w};
            #pragma unroll
            for (int i = 0; i < 8; i++)
                #pragma unroll
                for (int j = 0; j < 8; j++)
                    acc[i][j] += av[i]*bv[j];
        }
    }
    int c0 = g*64 + tx*8;
    float4 bb0 = *(const float4*)&bsamp[c0];
    float4 bb1 = *(const float4*)&bsamp[c0+4];
    #pragma unroll
    for (int i = 0; i < 8; i++) {
        int row = p0 + ty*8 + i;
        float4 o0, o1;
        o0.x = acc[i][0] + bb0.x; o0.y = acc[i][1] + bb0.y;
        o0.z = acc[i][2] + bb0.z; o0.w = acc[i][3] + bb0.w;
        o1.x = acc[i][4] + bb1.x; o1.y = acc[i][5] + bb1.y;
        o1.z = acc[i][6] + bb1.z; o1.w = acc[i][7] + bb1.w;
        *(float4*)&out[row*CC + c0]     = o0;
        *(float4*)&out[row*CC + c0 + 4] = o1;
    }
}

// ============================================================================
// K4: LayerNorm + residual, in place. Two-pass variance (stable).
// ============================================================================
__global__ void k4_ln(const float* __restrict__ x, const float* __restrict__ lng,
                      const float* __restrict__ lnb, float* __restrict__ out) {
    __shared__ float red[4];
    int pt = blockIdx.x, tid = threadIdx.x;
    const float* yp = out + pt*CC;
    const float* xp = x   + pt*CC;
    float v[4];
    float s1 = 0.f;
    #pragma unroll
    for (int j = 0; j < 4; j++) {
        v[j] = yp[j*128 + tid];
        s1 += v[j];
    }
    #pragma unroll
    for (int o = 16; o; o >>= 1) s1 += __shfl_xor_sync(0xFFFFFFFFu, s1, o);
    if ((tid & 31) == 0) red[tid>>5] = s1;
    __syncthreads();
    float mu = (red[0]+red[1]+red[2]+red[3]) * (1.f/512.f);
    __syncthreads();

    float s2 = 0.f;
    #pragma unroll
    for (int j = 0; j < 4; j++) { float d = v[j]-mu; s2 += d*d; }
    #pragma unroll
    for (int o = 16; o; o >>= 1) s2 += __shfl_xor_sync(0xFFFFFFFFu, s2, o);
    if ((tid & 31) == 0) red[tid>>5] = s2;
    __syncthreads();
    float var = (red[0]+red[1]+red[2]+red[3]) * (1.f/512.f);
    float rs  = rsqrtf(var + 1e-5f);
    #pragma unroll
    for (int j = 0; j < 4; j++) {
        int c = j*128 + tid;
        out[pt*CC + c] = (v[j]-mu)*rs*lng[c] + lnb[c] + xp[c];
    }
}

// ============================================================================
extern "C" void kernel_launch(void* const* d_in, const int* in_sizes, int n_in,
                              void* d_out, int out_size) {
    const float* x  = (const float*)d_in[0];
    const float* r  = (const float*)d_in[1];
    const float* I  = (const float*)d_in[2];
    const float* IX = (const float*)d_in[3];
    const float* IY = (const float*)d_in[4];
    const float* IT = (const float*)d_in[5];
    const float* Wr = (const float*)d_in[6];
    const float* br = (const float*)d_in[7];
    const float* Wm = (const float*)d_in[8];
    const float* bm = (const float*)d_in[9];
    const float* Ws = (const float*)d_in[10];
    const float* bs = (const float*)d_in[11];
    const float* lg = (const float*)d_in[12];
    const float* lb = (const float*)d_in[13];
    float* out = (float*)d_out;

    k0_transpose<<<dim3(12, 96, 8), dim3(32, 8)>>>(I, IX, IY, IT);
    k1_logits_rects<<<NPTS/K1_PTS, 256>>>(x, r, Wr, br, Wm, bm, out);
    k2_sample<<<NPTS/2, 128>>>(out);
    k3_gemm<<<dim3(NPTS/128, 8), 128>>>(Ws, bs, out);
    k4_ln<<<NPTS, 128>>>(x, lg, lb, out);
}

// round 13
// speedup vs baseline: 1.9333x; 1.0423x over previous
#include <cuda_runtime.h>

#define BB    8
#define NN    2048
#define NPTS  (BB*NN)        // 16384
#define CC    512
#define CIN   128
#define HH    96
#define WIW   96
#define IMG_ELEMS (BB*HH*WIW*CIN)   // 9437184

#define L0OFF (NPTS*CC)              // 8388608
#define L1OFF (L0OFF + NPTS*8)       // 8519680
#define L2OFF (L1OFF + NPTS*16)      // 8781824

// -------- scratch (static device allocation; no cudaMalloc allowed) --------
__device__ __align__(16) float g_TI [IMG_ELEMS];   // I  transposed to (b,x,y,c)
__device__ __align__(16) float g_TIT[IMG_ELEMS];   // IT transposed
__device__ __align__(16) float g_TJX[IMG_ELEMS];   // (IX - 0.5*I) transposed
__device__ __align__(16) float g_TJY[IMG_ELEMS];   // (IY - 0.5*I) transposed
__device__ __align__(16) float g_mask[NPTS*64];    // softmax mask, [pt][s*8+g]
__device__ __align__(16) float g_Z[NPTS*8*CIN];    // Z[pt][g][k]

// ============================================================================
// K0: transpose (B,Cin,H,W) -> (B,H,W,Cin) with fused JX/JY
// ============================================================================
__global__ void k0_transpose(const float* __restrict__ I, const float* __restrict__ IX,
                             const float* __restrict__ IY, const float* __restrict__ IT) {
    __shared__ float tI[32][33], tIX[32][33], tIY[32][33], tIT[32][33];
    int ct = blockIdx.x / 3, yt = blockIdx.x % 3;
    int xx = blockIdx.y, b = blockIdx.z;
    int tx = threadIdx.x, ty = threadIdx.y;
    #pragma unroll
    for (int rr = ty; rr < 32; rr += 8) {
        int c = ct*32 + rr;
        int y = yt*32 + tx;
        int src = ((b*CIN + c)*HH + xx)*WIW + y;
        tI [rr][tx] = I [src];
        tIX[rr][tx] = IX[src];
        tIY[rr][tx] = IY[src];
        tIT[rr][tx] = IT[src];
    }
    __syncthreads();
    #pragma unroll
    for (int rr = ty; rr < 32; rr += 8) {
        int c = ct*32 + tx;
        int y = yt*32 + rr;
        int dst = ((b*HH + xx)*WIW + y)*CIN + c;
        float vi = tI[tx][rr];
        g_TI [dst] = vi;
        g_TIT[dst] = tIT[tx][rr];
        g_TJX[dst] = tIX[tx][rr] - 0.5f*vi;
        g_TJY[dst] = tIY[tx][rr] - 0.5f*vi;
    }
}

// ============================================================================
// K1: fused (ratios | mask) logits + rect splits + softmax mask
// ============================================================================
#define K1_PTS 16
__global__ void k1_logits_rects(const float* __restrict__ x, const float* __restrict__ r,
                                const float* __restrict__ Wr, const float* __restrict__ br,
                                const float* __restrict__ Wm, const float* __restrict__ bm,
                                float* __restrict__ out) {
    __shared__ float xs[K1_PTS][516];   // padded (516 % 4 == 0 keeps float4 alignment)
    __shared__ float lg[K1_PTS][72];
    __shared__ float rects[K1_PTS][56]; // [0,8)=L0, [8,24)=L1, [24,56)=L2
    int tid = threadIdx.x;
    int p0  = blockIdx.x * K1_PTS;

    for (int i = tid; i < K1_PTS*CC; i += 256) {
        int p = i >> 9, k = i & 511;
        xs[p][k] = x[(p0+p)*CC + k];
    }
    __syncthreads();

    // mask logits: thread = (point, 4 cols); float4 loads; split-4 accumulation
    {
        int p = tid >> 4, q = tid & 15;     // q*4 = first col
        float4 a0 = {0,0,0,0}, a1 = {0,0,0,0}, a2 = {0,0,0,0}, a3 = {0,0,0,0};
        #pragma unroll 4
        for (int k = 0; k < CC; k += 4) {
            float4 xv = *(const float4*)&xs[p][k];
            float4 w0 = *(const float4*)&Wm[(k+0)*64 + q*4];
            float4 w1 = *(const float4*)&Wm[(k+1)*64 + q*4];
            float4 w2 = *(const float4*)&Wm[(k+2)*64 + q*4];
            float4 w3 = *(const float4*)&Wm[(k+3)*64 + q*4];
            a0.x += xv.x*w0.x; a0.y += xv.x*w0.y; a0.z += xv.x*w0.z; a0.w += xv.x*w0.w;
            a1.x += xv.y*w1.x; a1.y += xv.y*w1.y; a1.z += xv.y*w1.z; a1.w += xv.y*w1.w;
            a2.x += xv.z*w2.x; a2.y += xv.z*w2.y; a2.z += xv.z*w2.z; a2.w += xv.z*w2.w;
            a3.x += xv.w*w3.x; a3.y += xv.w*w3.y; a3.z += xv.w*w3.z; a3.w += xv.w*w3.w;
        }
        lg[p][7 + q*4 + 0] = (a0.x+a1.x) + (a2.x+a3.x);
        lg[p][7 + q*4 + 1] = (a0.y+a1.y) + (a2.y+a3.y);
        lg[p][7 + q*4 + 2] = (a0.z+a1.z) + (a2.z+a3.z);
        lg[p][7 + q*4 + 3] = (a0.w+a1.w) + (a2.w+a3.w);
    }

    // ratio logits: pairwise fp32 chunks of 8, summed into double
    if (tid < K1_PTS*7) {
        int p = tid / 7, j = tid % 7;
        double acc = 0.0;
        #pragma unroll 4
        for (int kb = 0; kb < CC; kb += 16) {
            float s0 = ((xs[p][kb+0]*Wr[(kb+0)*7+j] + xs[p][kb+1]*Wr[(kb+1)*7+j])
                      + (xs[p][kb+2]*Wr[(kb+2)*7+j] + xs[p][kb+3]*Wr[(kb+3)*7+j]))
                     + ((xs[p][kb+4]*Wr[(kb+4)*7+j] + xs[p][kb+5]*Wr[(kb+5)*7+j])
                      + (xs[p][kb+6]*Wr[(kb+6)*7+j] + xs[p][kb+7]*Wr[(kb+7)*7+j]));
            float s1 = ((xs[p][kb+8]*Wr[(kb+8)*7+j] + xs[p][kb+9]*Wr[(kb+9)*7+j])
                      + (xs[p][kb+10]*Wr[(kb+10)*7+j] + xs[p][kb+11]*Wr[(kb+11)*7+j]))
                     + ((xs[p][kb+12]*Wr[(kb+12)*7+j] + xs[p][kb+13]*Wr[(kb+13)*7+j])
                      + (xs[p][kb+14]*Wr[(kb+14)*7+j] + xs[p][kb+15]*Wr[(kb+15)*7+j]));
            acc += (double)s0 + (double)s1;
        }
        lg[p][j] = (float)acc;
    }
    __syncthreads();

    // rect splits: one thread per point (fp32, matching reference formula)
    if (tid < K1_PTS) {
        int gp = p0 + tid;
        float rat[7];
        #pragma unroll
        for (int i = 0; i < 7; i++)
            rat[i] = 1.f / (1.f + expf(-(lg[tid][i] + br[i])));
        float R0[4];
        #pragma unroll
        for (int i = 0; i < 4; i++) R0[i] = r[gp*4 + i];

        float A[2][4], Bv[4][4], Cv[8][4];
        {
            float mid = R0[0]*(1.f-rat[0]) + R0[2]*rat[0];
            A[0][0]=R0[0]; A[0][1]=R0[1]; A[0][2]=mid;   A[0][3]=R0[3];
            A[1][0]=mid;   A[1][1]=R0[1]; A[1][2]=R0[2]; A[1][3]=R0[3];
        }
        #pragma unroll
        for (int k = 0; k < 2; k++) {
            float rt  = rat[1+k];
            float mid = A[k][1]*(1.f-rt) + A[k][3]*rt;
            Bv[k][0]=A[k][0];   Bv[k][1]=A[k][1]; Bv[k][2]=A[k][2];   Bv[k][3]=mid;
            Bv[2+k][0]=A[k][0]; Bv[2+k][1]=mid;   Bv[2+k][2]=A[k][2]; Bv[2+k][3]=A[k][3];
        }
        #pragma unroll
        for (int k = 0; k < 4; k++) {
            float rt  = rat[3+k];
            float mid = Bv[k][0]*(1.f-rt) + Bv[k][2]*rt;
            Cv[k][0]=Bv[k][0]; Cv[k][1]=Bv[k][1]; Cv[k][2]=mid;      Cv[k][3]=Bv[k][3];
            Cv[4+k][0]=mid;    Cv[4+k][1]=Bv[k][1]; Cv[4+k][2]=Bv[k][2]; Cv[4+k][3]=Bv[k][3];
        }
        #pragma unroll
        for (int i = 0; i < 8;  i++) rects[tid][i]      = A[i>>2][i&3];
        #pragma unroll
        for (int i = 0; i < 16; i++) rects[tid][8+i]    = Bv[i>>2][i&3];
        #pragma unroll
        for (int i = 0; i < 32; i++) rects[tid][24+i]   = Cv[i>>2][i&3];
    }
    __syncthreads();

    // softmax over rects per (point, group)
    if (tid < K1_PTS*8) {
        int p = tid >> 3, g = tid & 7;
        float m[8], mx = -1e30f;
        #pragma unroll
        for (int s = 0; s < 8; s++) { m[s] = lg[p][7 + s*8 + g] + bm[s*8 + g]; mx = fmaxf(mx, m[s]); }
        float sum = 0.f;
        #pragma unroll
        for (int s = 0; s < 8; s++) { m[s] = expf(m[s]-mx); sum += m[s]; }
        float inv = 1.f / sum;
        #pragma unroll
        for (int s = 0; s < 8; s++) g_mask[(p0+p)*64 + s*8 + g] = m[s]*inv;
    }

    for (int i = tid; i < K1_PTS*8;  i += 256) out[L0OFF + p0*8  + i] = rects[i>>3][i&7];
    for (int i = tid; i < K1_PTS*16; i += 256) out[L1OFF + p0*16 + i] = rects[i>>4][8  + (i&15)];
    for (int i = tid; i < K1_PTS*32; i += 256) out[L2OFF + p0*32 + i] = rects[i>>5][24 + (i&31)];
}

// ============================================================================
// K2: integral-image sampling, 18-corner dedup + edge hoist, float2 channels
//     2 points/block, 64 threads/point, each thread owns 2 channels
// ============================================================================
__device__ __forceinline__ float corner_eval(float tit, float jxm, float jx0,
                                             float jym, float jy0,
                                             float timm, float tim0, float ti0m, float ti00,
                                             float wx1, float wx2, float wy1, float wy2,
                                             float eyv, float exv) {
    float v = tit;
    v -= wy1*jxm + wy2*jx0;
    v -= wx1*jym + wx2*jy0;
    v += eyv + exv;
    v += wx1*(wy1*timm + wy2*tim0) + wx2*(wy1*ti0m + wy2*ti00);
    return v;
}

__global__ void __launch_bounds__(128) k2_sample(const float* __restrict__ out) {
    __shared__ float rrs[2][32];
    __shared__ float msk[2][64];
    __shared__ int   sxX[2][7], sxXm[2][7], syY[2][4], syYm[2][4];
    __shared__ float swx1[2][7], swx2[2][7], swy1[2][4], swy2[2][4];
    int tid  = threadIdx.x;
    int half = tid >> 6, l = tid & 63;
    int pt   = blockIdx.x*2 + half;
    if (l < 32) rrs[half][l] = out[L2OFF + pt*32 + l] * 95.f;
    msk[half][l] = g_mask[pt*64 + l];
    __syncthreads();
    if (l < 7) {
        const int xsrc[7] = {0, 4, 22, 2, 6, 10, 14};
        float px = rrs[half][xsrc[l]];
        float Xf = ceilf(px);
        int X = (int)Xf, Xm = max(X-1, 0);
        float dx = Xf - px;
        float w1 = 0.5f*dx*dx;
        swx1[half][l] = w1; swx2[half][l] = dx - w1;
        sxX[half][l]  = X *(WIW*64);     // float2 units
        sxXm[half][l] = Xm*(WIW*64);
    } else if (l >= 8 && l < 12) {
        const int ysrc[4] = {1, 3, 7, 11};
        int t = l - 8;
        float py = rrs[half][ysrc[t]];
        float Yf = ceilf(py);
        int Y = (int)Yf, Ym = max(Y-1, 0);
        float dy = Yf - py;
        float w1 = 0.5f*dy*dy;
        swy1[half][t] = w1; swy2[half][t] = dy - w1;
        syY[half][t]  = Y *64;           // float2 units
        syYm[half][t] = Ym*64;
    }
    __syncthreads();

    const float2* TI2  = (const float2*)g_TI;
    const float2* TIT2 = (const float2*)g_TIT;
    const float2* TJX2 = (const float2*)g_TJX;
    const float2* TJY2 = (const float2*)g_TJY;
    int b = pt >> 11;
    int base2 = b*(HH*WIW*64) + l;      // float2 units; channel pair = l

    // edge terms (float2)
    float2 ey[4], ex[7];
    #pragma unroll
    for (int yi = 0; yi < 4; yi++) {
        float2 tm = TI2[base2 + syYm[half][yi]];
        float2 t0 = TI2[base2 + syY [half][yi]];
        float w1 = swy1[half][yi], w2 = swy2[half][yi];
        ey[yi].x = 0.5f*(w1*tm.x + w2*t0.x);
        ey[yi].y = 0.5f*(w1*tm.y + w2*t0.y);
    }
    #pragma unroll
    for (int xi = 0; xi < 7; xi++) {
        float2 tm = TI2[base2 + sxXm[half][xi]];
        float2 t0 = TI2[base2 + sxX [half][xi]];
        float w1 = swx1[half][xi], w2 = swx2[half][xi];
        ex[xi].x = 0.5f*(w1*tm.x + w2*t0.x);
        ex[xi].y = 0.5f*(w1*tm.y + w2*t0.y);
    }

    // 18 unique corners
    const int CXI[18] = {0,0,1,1,3,3, 1,2,2,4,4, 0,1,5,5, 2,6,6};
    const int CYI[18] = {0,1,0,1,0,1, 2,0,2,0,2, 3,3,1,3, 3,2,3};
    float2 c[18];
    #pragma unroll
    for (int i = 0; i < 18; i++) {
        int xi = CXI[i], yi = CYI[i];
        int oX = sxX[half][xi], oXm = sxXm[half][xi];
        int oY = syY[half][yi], oYm = syYm[half][yi];
        float wx1 = swx1[half][xi], wx2 = swx2[half][xi];
        float wy1 = swy1[half][yi], wy2 = swy2[half][yi];
        int aXY   = base2 + oX  + oY;
        int aXYm  = base2 + oX  + oYm;
        int aXmY  = base2 + oXm + oY;
        int aXmYm = base2 + oXm + oYm;
        float2 tit  = TIT2[aXY];
        float2 jxm  = TJX2[aXYm], jx0 = TJX2[aXY];
        float2 jym  = TJY2[aXmY], jy0 = TJY2[aXY];
        float2 timm = TI2[aXmYm], tim0 = TI2[aXmY];
        float2 ti0m = TI2[aXYm],  ti00 = TI2[aXY];
        c[i].x = corner_eval(tit.x, jxm.x, jx0.x, jym.x, jy0.x,
                             timm.x, tim0.x, ti0m.x, ti00.x,
                             wx1, wx2, wy1, wy2, ey[yi].x, ex[xi].x);
        c[i].y = corner_eval(tit.y, jxm.y, jx0.y, jym.y, jy0.y,
                             timm.y, tim0.y, ti0m.y, ti00.y,
                             wx1, wx2, wy1, wy2, ey[yi].y, ex[xi].y);
    }

    // rect combines in exact reference order, then mask-weighted Z
    const int RA[8] = {5,10,14,17, 3, 8,12,15};
    const int RB[8] = {1, 6,11,12, 5,10,14,17};
    const int RC[8] = {4, 9,13,16, 2, 7, 3, 8};
    const int RD[8] = {0, 2, 1, 6, 4, 9,13,16};
    float2 zacc[8];
    #pragma unroll
    for (int g = 0; g < 8; g++) { zacc[g].x = 0.f; zacc[g].y = 0.f; }
    #pragma unroll
    for (int s = 0; s < 8; s++) {
        float x1 = rrs[half][s*4+0], y1 = rrs[half][s*4+1];
        float x2 = rrs[half][s*4+2], y2 = rrs[half][s*4+3];
        float inva = 1.f / (fabsf((x1-x2)*(y1-y2)) + 1e-9f);
        float Svx = (((c[RA[s]].x - c[RB[s]].x) - c[RC[s]].x) + c[RD[s]].x) * inva;
        float Svy = (((c[RA[s]].y - c[RB[s]].y) - c[RC[s]].y) + c[RD[s]].y) * inva;
        #pragma unroll
        for (int g = 0; g < 8; g++) {
            float m = msk[half][s*8+g];
            zacc[g].x += m*Svx;
            zacc[g].y += m*Svy;
        }
    }
    float2* gZ2 = (float2*)g_Z;
    #pragma unroll
    for (int g = 0; g < 8; g++)
        gZ2[(pt*8 + g)*64 + l] = zacc[g];
}

// ============================================================================
// K3: per-group GEMM, 128 pts x 64 cols per block, 256 threads, 8x4 per thread
//     Zs transposed [kk][p] pad 136 (stride 8 mod 32: 4-way fill conflicts,
//     16B-aligned float4 rows). 32 FFMA : 3 LDS.128 per thread-kstep.
// ============================================================================
__global__ void __launch_bounds__(256, 3) k3_gemm(const float* __restrict__ Wsamp,
                                                  const float* __restrict__ bsamp,
                                                  float* __restrict__ out) {
    __shared__ float Zs[64][136];
    __shared__ float Wt[64][68];
    int p0  = blockIdx.x * 128;
    int g   = blockIdx.y;
    int tid = threadIdx.x;
    int tx  = tid & 15, ty = tid >> 4;   // tx: 16 col-quads (64 cols), ty: 16 row-octets (128 rows)
    float acc[8][4] = {};
    for (int kb = 0; kb < CIN; kb += 64) {
        __syncthreads();
        for (int i = tid; i < 8192; i += 256) {
            int p = i >> 6, kk = i & 63;
            Zs[kk][p] = g_Z[((p0+p)*8 + g)*CIN + kb + kk];
        }
        for (int i = tid; i < 4096; i += 256) {
            int kk = i >> 6, cc = i & 63;
            Wt[kk][cc] = Wsamp[(kb+kk)*CC + g*64 + cc];
        }
        __syncthreads();
        #pragma unroll 4
        for (int kk = 0; kk < 64; kk++) {
            float4 a0 = *(const float4*)&Zs[kk][ty*8];
            float4 a1 = *(const float4*)&Zs[kk][ty*8+4];
            float4 bv = *(const float4*)&Wt[kk][tx*4];
            acc[0][0] += a0.x*bv.x; acc[0][1] += a0.x*bv.y; acc[0][2] += a0.x*bv.z; acc[0][3] += a0.x*bv.w;
            acc[1][0] += a0.y*bv.x; acc[1][1] += a0.y*bv.y; acc[1][2] += a0.y*bv.z; acc[1][3] += a0.y*bv.w;
            acc[2][0] += a0.z*bv.x; acc[2][1] += a0.z*bv.y; acc[2][2] += a0.z*bv.z; acc[2][3] += a0.z*bv.w;
            acc[3][0] += a0.w*bv.x; acc[3][1] += a0.w*bv.y; acc[3][2] += a0.w*bv.z; acc[3][3] += a0.w*bv.w;
            acc[4][0] += a1.x*bv.x; acc[4][1] += a1.x*bv.y; acc[4][2] += a1.x*bv.z; acc[4][3] += a1.x*bv.w;
            acc[5][0] += a1.y*bv.x; acc[5][1] += a1.y*bv.y; acc[5][2] += a1.y*bv.z; acc[5][3] += a1.y*bv.w;
            acc[6][0] += a1.z*bv.x; acc[6][1] += a1.z*bv.y; acc[6][2] += a1.z*bv.z; acc[6][3] += a1.z*bv.w;
            acc[7][0] += a1.w*bv.x; acc[7][1] += a1.w*bv.y; acc[7][2] += a1.w*bv.z; acc[7][3] += a1.w*bv.w;
        }
    }
    int c0 = g*64 + tx*4;
    float4 bb = *(const float4*)&bsamp[c0];
    #pragma unroll
    for (int i = 0; i < 8; i++) {
        int row = p0 + ty*8 + i;
        float4 o;
        o.x = acc[i][0] + bb.x; o.y = acc[i][1] + bb.y;
        o.z = acc[i][2] + bb.z; o.w = acc[i][3] + bb.w;
        *(float4*)&out[row*CC + c0] = o;
    }
}

// ============================================================================
// K4: LayerNorm + residual, in place. Two-pass variance (stable).
// ============================================================================
__global__ void k4_ln(const float* __restrict__ x, const float* __restrict__ lng,
                      const float* __restrict__ lnb, float* __restrict__ out) {
    __shared__ float red[4];
    int pt = blockIdx.x, tid = threadIdx.x;
    const float* yp = out + pt*CC;
    const float* xp = x   + pt*CC;
    float v[4];
    float s1 = 0.f;
    #pragma unroll
    for (int j = 0; j < 4; j++) {
        v[j] = yp[j*128 + tid];
        s1 += v[j];
    }
    #pragma unroll
    for (int o = 16; o; o >>= 1) s1 += __shfl_xor_sync(0xFFFFFFFFu, s1, o);
    if ((tid & 31) == 0) red[tid>>5] = s1;
    __syncthreads();
    float mu = (red[0]+red[1]+red[2]+red[3]) * (1.f/512.f);
    __syncthreads();

    float s2 = 0.f;
    #pragma unroll
    for (int j = 0; j < 4; j++) { float d = v[j]-mu; s2 += d*d; }
    #pragma unroll
    for (int o = 16; o; o >>= 1) s2 += __shfl_xor_sync(0xFFFFFFFFu, s2, o);
    if ((tid & 31) == 0) red[tid>>5] = s2;
    __syncthreads();
    float var = (red[0]+red[1]+red[2]+red[3]) * (1.f/512.f);
    float rs  = rsqrtf(var + 1e-5f);
    #pragma unroll
    for (int j = 0; j < 4; j++) {
        int c = j*128 + tid;
        out[pt*CC + c] = (v[j]-mu)*rs*lng[c] + lnb[c] + xp[c];
    }
}

// ============================================================================
extern "C" void kernel_launch(void* const* d_in, const int* in_sizes, int n_in,
                              void* d_out, int out_size) {
    const float* x  = (const float*)d_in[0];
    const float* r  = (const float*)d_in[1];
    const float* I  = (const float*)d_in[2];
    const float* IX = (const float*)d_in[3];
    const float* IY = (const float*)d_in[4];
    const float* IT = (const float*)d_in[5];
    const float* Wr = (const float*)d_in[6];
    const float* br = (const float*)d_in[7];
    const float* Wm = (const float*)d_in[8];
    const float* bm = (const float*)d_in[9];
    const float* Ws = (const float*)d_in[10];
    const float* bs = (const float*)d_in[11];
    const float* lg = (const float*)d_in[12];
    const float* lb = (const float*)d_in[13];
    float* out = (float*)d_out;

    k0_transpose<<<dim3(12, 96, 8), dim3(32, 8)>>>(I, IX, IY, IT);
    k1_logits_rects<<<NPTS/K1_PTS, 256>>>(x, r, Wr, br, Wm, bm, out);
    k2_sample<<<NPTS/2, 128>>>(out);
    k3_gemm<<<dim3(NPTS/128, 8), 256>>>(Ws, bs, out);
    k4_ln<<<NPTS, 128>>>(x, lg, lb, out);
}

// round 14
// speedup vs baseline: 1.9882x; 1.0284x over previous
#include <cuda_runtime.h>

#define BB    8
#define NN    2048
#define NPTS  (BB*NN)        // 16384
#define CC    512
#define CIN   128
#define HH    96
#define WIW   96
#define IMG_ELEMS (BB*HH*WIW*CIN)   // 9437184

#define L0OFF (NPTS*CC)              // 8388608
#define L1OFF (L0OFF + NPTS*8)       // 8519680
#define L2OFF (L1OFF + NPTS*16)      // 8781824

// -------- scratch (static device allocation; no cudaMalloc allowed) --------
__device__ __align__(16) float g_TI [IMG_ELEMS];   // I  transposed to (b,x,y,c)
__device__ __align__(16) float g_TIT[IMG_ELEMS];   // IT transposed
__device__ __align__(16) float g_TJX[IMG_ELEMS];   // (IX - 0.5*I) transposed
__device__ __align__(16) float g_TJY[IMG_ELEMS];   // (IY - 0.5*I) transposed
__device__ __align__(16) float g_mask[NPTS*64];    // softmax mask, [pt][s*8+g]
__device__ __align__(16) float g_Z[NPTS*8*CIN];    // Z[pt][g][k]

// ============================================================================
// K0: transpose (B,Cin,H,W) -> (B,H,W,Cin) with fused JX/JY
// ============================================================================
__global__ void k0_transpose(const float* __restrict__ I, const float* __restrict__ IX,
                             const float* __restrict__ IY, const float* __restrict__ IT) {
    __shared__ float tI[32][33], tIX[32][33], tIY[32][33], tIT[32][33];
    int ct = blockIdx.x / 3, yt = blockIdx.x % 3;
    int xx = blockIdx.y, b = blockIdx.z;
    int tx = threadIdx.x, ty = threadIdx.y;
    #pragma unroll
    for (int rr = ty; rr < 32; rr += 8) {
        int c = ct*32 + rr;
        int y = yt*32 + tx;
        int src = ((b*CIN + c)*HH + xx)*WIW + y;
        tI [rr][tx] = I [src];
        tIX[rr][tx] = IX[src];
        tIY[rr][tx] = IY[src];
        tIT[rr][tx] = IT[src];
    }
    __syncthreads();
    #pragma unroll
    for (int rr = ty; rr < 32; rr += 8) {
        int c = ct*32 + tx;
        int y = yt*32 + rr;
        int dst = ((b*HH + xx)*WIW + y)*CIN + c;
        float vi = tI[tx][rr];
        g_TI [dst] = vi;
        g_TIT[dst] = tIT[tx][rr];
        g_TJX[dst] = tIX[tx][rr] - 0.5f*vi;
        g_TJY[dst] = tIY[tx][rr] - 0.5f*vi;
    }
}

// ============================================================================
// K1: fused (ratios | mask) logits + rect splits + softmax mask
// ============================================================================
#define K1_PTS 16
__global__ void k1_logits_rects(const float* __restrict__ x, const float* __restrict__ r,
                                const float* __restrict__ Wr, const float* __restrict__ br,
                                const float* __restrict__ Wm, const float* __restrict__ bm,
                                float* __restrict__ out) {
    __shared__ float xs[K1_PTS][516];   // padded (516 % 4 == 0 keeps float4 alignment)
    __shared__ float lg[K1_PTS][72];
    __shared__ float rects[K1_PTS][56]; // [0,8)=L0, [8,24)=L1, [24,56)=L2
    int tid = threadIdx.x;
    int p0  = blockIdx.x * K1_PTS;

    for (int i = tid; i < K1_PTS*CC; i += 256) {
        int p = i >> 9, k = i & 511;
        xs[p][k] = x[(p0+p)*CC + k];
    }
    __syncthreads();

    // mask logits: thread = (point, 4 cols); float4 loads; split-4 accumulation
    {
        int p = tid >> 4, q = tid & 15;     // q*4 = first col
        float4 a0 = {0,0,0,0}, a1 = {0,0,0,0}, a2 = {0,0,0,0}, a3 = {0,0,0,0};
        #pragma unroll 4
        for (int k = 0; k < CC; k += 4) {
            float4 xv = *(const float4*)&xs[p][k];
            float4 w0 = *(const float4*)&Wm[(k+0)*64 + q*4];
            float4 w1 = *(const float4*)&Wm[(k+1)*64 + q*4];
            float4 w2 = *(const float4*)&Wm[(k+2)*64 + q*4];
            float4 w3 = *(const float4*)&Wm[(k+3)*64 + q*4];
            a0.x += xv.x*w0.x; a0.y += xv.x*w0.y; a0.z += xv.x*w0.z; a0.w += xv.x*w0.w;
            a1.x += xv.y*w1.x; a1.y += xv.y*w1.y; a1.z += xv.y*w1.z; a1.w += xv.y*w1.w;
            a2.x += xv.z*w2.x; a2.y += xv.z*w2.y; a2.z += xv.z*w2.z; a2.w += xv.z*w2.w;
            a3.x += xv.w*w3.x; a3.y += xv.w*w3.y; a3.z += xv.w*w3.z; a3.w += xv.w*w3.w;
        }
        lg[p][7 + q*4 + 0] = (a0.x+a1.x) + (a2.x+a3.x);
        lg[p][7 + q*4 + 1] = (a0.y+a1.y) + (a2.y+a3.y);
        lg[p][7 + q*4 + 2] = (a0.z+a1.z) + (a2.z+a3.z);
        lg[p][7 + q*4 + 3] = (a0.w+a1.w) + (a2.w+a3.w);
    }

    // ratio logits: pairwise fp32 chunks of 8, summed into double
    if (tid < K1_PTS*7) {
        int p = tid / 7, j = tid % 7;
        double acc = 0.0;
        #pragma unroll 4
        for (int kb = 0; kb < CC; kb += 16) {
            float s0 = ((xs[p][kb+0]*Wr[(kb+0)*7+j] + xs[p][kb+1]*Wr[(kb+1)*7+j])
                      + (xs[p][kb+2]*Wr[(kb+2)*7+j] + xs[p][kb+3]*Wr[(kb+3)*7+j]))
                     + ((xs[p][kb+4]*Wr[(kb+4)*7+j] + xs[p][kb+5]*Wr[(kb+5)*7+j])
                      + (xs[p][kb+6]*Wr[(kb+6)*7+j] + xs[p][kb+7]*Wr[(kb+7)*7+j]));
            float s1 = ((xs[p][kb+8]*Wr[(kb+8)*7+j] + xs[p][kb+9]*Wr[(kb+9)*7+j])
                      + (xs[p][kb+10]*Wr[(kb+10)*7+j] + xs[p][kb+11]*Wr[(kb+11)*7+j]))
                     + ((xs[p][kb+12]*Wr[(kb+12)*7+j] + xs[p][kb+13]*Wr[(kb+13)*7+j])
                      + (xs[p][kb+14]*Wr[(kb+14)*7+j] + xs[p][kb+15]*Wr[(kb+15)*7+j]));
            acc += (double)s0 + (double)s1;
        }
        lg[p][j] = (float)acc;
    }
    __syncthreads();

    // rect splits: one thread per point (fp32, matching reference formula)
    if (tid < K1_PTS) {
        int gp = p0 + tid;
        float rat[7];
        #pragma unroll
        for (int i = 0; i < 7; i++)
            rat[i] = 1.f / (1.f + expf(-(lg[tid][i] + br[i])));
        float R0[4];
        #pragma unroll
        for (int i = 0; i < 4; i++) R0[i] = r[gp*4 + i];

        float A[2][4], Bv[4][4], Cv[8][4];
        {
            float mid = R0[0]*(1.f-rat[0]) + R0[2]*rat[0];
            A[0][0]=R0[0]; A[0][1]=R0[1]; A[0][2]=mid;   A[0][3]=R0[3];
            A[1][0]=mid;   A[1][1]=R0[1]; A[1][2]=R0[2]; A[1][3]=R0[3];
        }
        #pragma unroll
        for (int k = 0; k < 2; k++) {
            float rt  = rat[1+k];
            float mid = A[k][1]*(1.f-rt) + A[k][3]*rt;
            Bv[k][0]=A[k][0];   Bv[k][1]=A[k][1]; Bv[k][2]=A[k][2];   Bv[k][3]=mid;
            Bv[2+k][0]=A[k][0]; Bv[2+k][1]=mid;   Bv[2+k][2]=A[k][2]; Bv[2+k][3]=A[k][3];
        }
        #pragma unroll
        for (int k = 0; k < 4; k++) {
            float rt  = rat[3+k];
            float mid = Bv[k][0]*(1.f-rt) + Bv[k][2]*rt;
            Cv[k][0]=Bv[k][0]; Cv[k][1]=Bv[k][1]; Cv[k][2]=mid;      Cv[k][3]=Bv[k][3];
            Cv[4+k][0]=mid;    Cv[4+k][1]=Bv[k][1]; Cv[4+k][2]=Bv[k][2]; Cv[4+k][3]=Bv[k][3];
        }
        #pragma unroll
        for (int i = 0; i < 8;  i++) rects[tid][i]      = A[i>>2][i&3];
        #pragma unroll
        for (int i = 0; i < 16; i++) rects[tid][8+i]    = Bv[i>>2][i&3];
        #pragma unroll
        for (int i = 0; i < 32; i++) rects[tid][24+i]   = Cv[i>>2][i&3];
    }
    __syncthreads();

    // softmax over rects per (point, group)
    if (tid < K1_PTS*8) {
        int p = tid >> 3, g = tid & 7;
        float m[8], mx = -1e30f;
        #pragma unroll
        for (int s = 0; s < 8; s++) { m[s] = lg[p][7 + s*8 + g] + bm[s*8 + g]; mx = fmaxf(mx, m[s]); }
        float sum = 0.f;
        #pragma unroll
        for (int s = 0; s < 8; s++) { m[s] = expf(m[s]-mx); sum += m[s]; }
        float inv = 1.f / sum;
        #pragma unroll
        for (int s = 0; s < 8; s++) g_mask[(p0+p)*64 + s*8 + g] = m[s]*inv;
    }

    for (int i = tid; i < K1_PTS*8;  i += 256) out[L0OFF + p0*8  + i] = rects[i>>3][i&7];
    for (int i = tid; i < K1_PTS*16; i += 256) out[L1OFF + p0*16 + i] = rects[i>>4][8  + (i&15)];
    for (int i = tid; i < K1_PTS*32; i += 256) out[L2OFF + p0*32 + i] = rects[i>>5][24 + (i&31)];
}

// ============================================================================
// K2: integral-image sampling, 18-corner dedup, edge terms DROPPED (they
//     cancel identically in the 4-corner rect combine), scatter-add into 8
//     Sraw accumulators (no c[18] storage). float2 channels, 2 pts/block.
//     162 LDG.64 per thread.
// ============================================================================
__global__ void __launch_bounds__(128) k2_sample(const float* __restrict__ out) {
    __shared__ float rrs[2][32];
    __shared__ float msk[2][64];
    __shared__ int   sxX[2][7], sxXm[2][7], syY[2][4], syYm[2][4];
    __shared__ float swx1[2][7], swx2[2][7], swy1[2][4], swy2[2][4];
    int tid  = threadIdx.x;
    int half = tid >> 6, l = tid & 63;
    int pt   = blockIdx.x*2 + half;
    if (l < 32) rrs[half][l] = out[L2OFF + pt*32 + l] * 95.f;
    msk[half][l] = g_mask[pt*64 + l];
    __syncthreads();
    if (l < 7) {
        const int xsrc[7] = {0, 4, 22, 2, 6, 10, 14};
        float px = rrs[half][xsrc[l]];
        float Xf = ceilf(px);
        int X = (int)Xf, Xm = max(X-1, 0);
        float dx = Xf - px;
        float w1 = 0.5f*dx*dx;
        swx1[half][l] = w1; swx2[half][l] = dx - w1;
        sxX[half][l]  = X *(WIW*64);     // float2 units
        sxXm[half][l] = Xm*(WIW*64);
    } else if (l >= 8 && l < 12) {
        const int ysrc[4] = {1, 3, 7, 11};
        int t = l - 8;
        float py = rrs[half][ysrc[t]];
        float Yf = ceilf(py);
        int Y = (int)Yf, Ym = max(Y-1, 0);
        float dy = Yf - py;
        float w1 = 0.5f*dy*dy;
        swy1[half][t] = w1; swy2[half][t] = dy - w1;
        syY[half][t]  = Y *64;           // float2 units
        syYm[half][t] = Ym*64;
    }
    __syncthreads();

    const float2* TI2  = (const float2*)g_TI;
    const float2* TIT2 = (const float2*)g_TIT;
    const float2* TJX2 = (const float2*)g_TJX;
    const float2* TJY2 = (const float2*)g_TJY;
    int b = pt >> 11;
    int base2 = b*(HH*WIW*64) + l;      // float2 units; channel pair = l

    // corner (xi, yi) index tables and per-corner scatter targets/signs.
    // Each corner feeds at most 2 rects: Sraw[U0] += G0*v, Sraw[U1] += G1*v.
    const int   CXI[18] = {0,0,1,1,3,3, 1,2,2,4,4, 0,1,5,5, 2,6,6};
    const int   CYI[18] = {0,1,0,1,0,1, 2,0,2,0,2, 3,3,1,3, 3,2,3};
    const int   U0 [18] = {0,0,1,4,0,0, 1,5,5,1,1, 2,6,2,2, 7,3,3};
    const float G0 [18] = {+1.f,-1.f,+1.f,+1.f,-1.f,+1.f, -1.f,-1.f,+1.f,-1.f,+1.f,
                           -1.f,+1.f,-1.f,+1.f, +1.f,-1.f,+1.f};
    const int   U1 [18] = {0,2,4,6,4,4, 3,0,7,5,5, 0,3,6,6, 0,7,7};
    const float G1 [18] = {0.f,+1.f,-1.f,-1.f,+1.f,-1.f, +1.f,0.f,-1.f,+1.f,-1.f,
                           0.f,-1.f,+1.f,-1.f, 0.f,+1.f,-1.f};

    float2 Sraw[8];
    #pragma unroll
    for (int s = 0; s < 8; s++) { Sraw[s].x = 0.f; Sraw[s].y = 0.f; }

    #pragma unroll
    for (int i = 0; i < 18; i++) {
        int xi = CXI[i], yi = CYI[i];
        int oX = sxX[half][xi], oXm = sxXm[half][xi];
        int oY = syY[half][yi], oYm = syYm[half][yi];
        float wx1 = swx1[half][xi], wx2 = swx2[half][xi];
        float wy1 = swy1[half][yi], wy2 = swy2[half][yi];
        int aXY   = base2 + oX  + oY;
        int aXYm  = base2 + oX  + oYm;
        int aXmY  = base2 + oXm + oY;
        int aXmYm = base2 + oXm + oYm;
        float2 tit  = TIT2[aXY];
        float2 jxm  = TJX2[aXYm], jx0 = TJX2[aXY];
        float2 jym  = TJY2[aXmY], jy0 = TJY2[aXY];
        float2 timm = TI2[aXmYm], tim0 = TI2[aXmY];
        float2 ti0m = TI2[aXYm],  ti00 = TI2[aXY];
        float vx = tit.x
                 - (wy1*jxm.x + wy2*jx0.x)
                 - (wx1*jym.x + wx2*jy0.x)
                 + (wx1*(wy1*timm.x + wy2*tim0.x) + wx2*(wy1*ti0m.x + wy2*ti00.x));
        float vy = tit.y
                 - (wy1*jxm.y + wy2*jx0.y)
                 - (wx1*jym.y + wx2*jy0.y)
                 + (wx1*(wy1*timm.y + wy2*tim0.y) + wx2*(wy1*ti0m.y + wy2*ti00.y));
        Sraw[U0[i]].x += G0[i]*vx;
        Sraw[U0[i]].y += G0[i]*vy;
        Sraw[U1[i]].x += G1[i]*vx;
        Sraw[U1[i]].y += G1[i]*vy;
    }

    // mask-weighted combine
    float2 zacc[8];
    #pragma unroll
    for (int g = 0; g < 8; g++) { zacc[g].x = 0.f; zacc[g].y = 0.f; }
    #pragma unroll
    for (int s = 0; s < 8; s++) {
        float x1 = rrs[half][s*4+0], y1 = rrs[half][s*4+1];
        float x2 = rrs[half][s*4+2], y2 = rrs[half][s*4+3];
        float inva = 1.f / (fabsf((x1-x2)*(y1-y2)) + 1e-9f);
        float Svx = Sraw[s].x * inva;
        float Svy = Sraw[s].y * inva;
        #pragma unroll
        for (int g = 0; g < 8; g++) {
            float m = msk[half][s*8+g];
            zacc[g].x += m*Svx;
            zacc[g].y += m*Svy;
        }
    }
    float2* gZ2 = (float2*)g_Z;
    #pragma unroll
    for (int g = 0; g < 8; g++)
        gZ2[(pt*8 + g)*64 + l] = zacc[g];
}

// ============================================================================
// K3: per-group GEMM, 64 pts x 64 cols per block, 256 threads, 4x4 per thread
//     (the R10-measured 67.8us configuration: Zs transposed [kk][p], pad 68)
// ============================================================================
__global__ void k3_gemm(const float* __restrict__ Wsamp, const float* __restrict__ bsamp,
                        float* __restrict__ out) {
    __shared__ float Zs[64][68];
    __shared__ float Wt[64][68];
    int p0  = blockIdx.x * 64;
    int g   = blockIdx.y;
    int tid = threadIdx.x;
    int tx  = tid & 15, ty = tid >> 4;
    float acc[4][4] = {};
    for (int kb = 0; kb < CIN; kb += 64) {
        __syncthreads();
        for (int i = tid; i < 4096; i += 256) {
            int p = i >> 6, kk = i & 63;
            Zs[kk][p] = g_Z[((p0+p)*8 + g)*CIN + kb + kk];
        }
        for (int i = tid; i < 4096; i += 256) {
            int kk = i >> 6, cc = i & 63;
            Wt[kk][cc] = Wsamp[(kb+kk)*CC + g*64 + cc];
        }
        __syncthreads();
        #pragma unroll 8
        for (int kk = 0; kk < 64; kk++) {
            float4 av = *(const float4*)&Zs[kk][ty*4];
            float4 bv = *(const float4*)&Wt[kk][tx*4];
            acc[0][0] += av.x*bv.x; acc[0][1] += av.x*bv.y; acc[0][2] += av.x*bv.z; acc[0][3] += av.x*bv.w;
            acc[1][0] += av.y*bv.x; acc[1][1] += av.y*bv.y; acc[1][2] += av.y*bv.z; acc[1][3] += av.y*bv.w;
            acc[2][0] += av.z*bv.x; acc[2][1] += av.z*bv.y; acc[2][2] += av.z*bv.z; acc[2][3] += av.z*bv.w;
            acc[3][0] += av.w*bv.x; acc[3][1] += av.w*bv.y; acc[3][2] += av.w*bv.z; acc[3][3] += av.w*bv.w;
        }
    }
    int c0 = g*64 + tx*4;
    float4 bb = *(const float4*)&bsamp[c0];
    #pragma unroll
    for (int i = 0; i < 4; i++) {
        int row = p0 + ty*4 + i;
        float4 o;
        o.x = acc[i][0] + bb.x; o.y = acc[i][1] + bb.y;
        o.z = acc[i][2] + bb.z; o.w = acc[i][3] + bb.w;
        *(float4*)&out[row*CC + c0] = o;
    }
}

// ============================================================================
// K4: LayerNorm + residual, in place. Two-pass variance (stable).
// ============================================================================
__global__ void k4_ln(const float* __restrict__ x, const float* __restrict__ lng,
                      const float* __restrict__ lnb, float* __restrict__ out) {
    __shared__ float red[4];
    int pt = blockIdx.x, tid = threadIdx.x;
    const float* yp = out + pt*CC;
    const float* xp = x   + pt*CC;
    float v[4];
    float s1 = 0.f;
    #pragma unroll
    for (int j = 0; j < 4; j++) {
        v[j] = yp[j*128 + tid];
        s1 += v[j];
    }
    #pragma unroll
    for (int o = 16; o; o >>= 1) s1 += __shfl_xor_sync(0xFFFFFFFFu, s1, o);
    if ((tid & 31) == 0) red[tid>>5] = s1;
    __syncthreads();
    float mu = (red[0]+red[1]+red[2]+red[3]) * (1.f/512.f);
    __syncthreads();

    float s2 = 0.f;
    #pragma unroll
    for (int j = 0; j < 4; j++) { float d = v[j]-mu; s2 += d*d; }
    #pragma unroll
    for (int o = 16; o; o >>= 1) s2 += __shfl_xor_sync(0xFFFFFFFFu, s2, o);
    if ((tid & 31) == 0) red[tid>>5] = s2;
    __syncthreads();
    float var = (red[0]+red[1]+red[2]+red[3]) * (1.f/512.f);
    float rs  = rsqrtf(var + 1e-5f);
    #pragma unroll
    for (int j = 0; j < 4; j++) {
        int c = j*128 + tid;
        out[pt*CC + c] = (v[j]-mu)*rs*lng[c] + lnb[c] + xp[c];
    }
}

// ============================================================================
extern "C" void kernel_launch(void* const* d_in, const int* in_sizes, int n_in,
                              void* d_out, int out_size) {
    const float* x  = (const float*)d_in[0];
    const float* r  = (const float*)d_in[1];
    const float* I  = (const float*)d_in[2];
    const float* IX = (const float*)d_in[3];
    const float* IY = (const float*)d_in[4];
    const float* IT = (const float*)d_in[5];
    const float* Wr = (const float*)d_in[6];
    const float* br = (const float*)d_in[7];
    const float* Wm = (const float*)d_in[8];
    const float* bm = (const float*)d_in[9];
    const float* Ws = (const float*)d_in[10];
    const float* bs = (const float*)d_in[11];
    const float* lg = (const float*)d_in[12];
    const float* lb = (const float*)d_in[13];
    float* out = (float*)d_out;

    k0_transpose<<<dim3(12, 96, 8), dim3(32, 8)>>>(I, IX, IY, IT);
    k1_logits_rects<<<NPTS/K1_PTS, 256>>>(x, r, Wr, br, Wm, bm, out);
    k2_sample<<<NPTS/2, 128>>>(out);
    k3_gemm<<<dim3(NPTS/64, 8), 256>>>(Ws, bs, out);
    k4_ln<<<NPTS, 128>>>(x, lg, lb, out);
}

// round 16
// speedup vs baseline: 2.4467x; 1.2306x over previous
#include <cuda_runtime.h>

#define BB    8
#define NN    2048
#define NPTS  (BB*NN)        // 16384
#define CC    512
#define CIN   128
#define HH    96
#define WIW   96
#define IMG_ELEMS (BB*HH*WIW*CIN)   // 9437184

#define L0OFF (NPTS*CC)              // 8388608
#define L1OFF (L0OFF + NPTS*8)       // 8519680
#define L2OFF (L1OFF + NPTS*16)      // 8781824

// -------- scratch (static device allocation; no cudaMalloc allowed) --------
__device__ __align__(16) float g_TI [IMG_ELEMS];   // I  transposed to (b,x,y,c)
__device__ __align__(16) float g_TIT[IMG_ELEMS];   // IT transposed
__device__ __align__(16) float g_TJX[IMG_ELEMS];   // (IX - 0.5*I) transposed
__device__ __align__(16) float g_TJY[IMG_ELEMS];   // (IY - 0.5*I) transposed
__device__ __align__(16) float g_mask[NPTS*64];    // softmax mask, [pt][s*8+g]
__device__ __align__(16) float g_Z[NPTS*8*CIN];    // Z[pt][g][k]

#define K1_PTS 16
#define K0_BLOCKS 9216               // 12 * 96 * 8
#define K1_BLOCKS (NPTS/K1_PTS)      // 1024
#define K01_BLOCKS (K0_BLOCKS + K1_BLOCKS)  // 10240 (k1 = every 10th block)

// ============================================================================
// K01: fused transpose (k0 path) + logits/rects (k1 path), block-level dispatch.
//      k1 blocks are interleaved (blockIdx % 10 == 9) so HBM-bound transpose
//      work overlaps FFMA-bound logit work within each wave.
// ============================================================================
union SmemK01 {
    struct { float tI[32][33], tIX[32][33], tIY[32][33], tIT[32][33]; } a;
    struct { float xs[K1_PTS][516]; float lg[K1_PTS][72]; float rects[K1_PTS][56]; } b;
};

__global__ void __launch_bounds__(256) k01_fused(
        const float* __restrict__ I, const float* __restrict__ IX,
        const float* __restrict__ IY, const float* __restrict__ IT,
        const float* __restrict__ x, const float* __restrict__ r,
        const float* __restrict__ Wr, const float* __restrict__ br,
        const float* __restrict__ Wm, const float* __restrict__ bm,
        float* __restrict__ out) {
    __shared__ SmemK01 sm;
    int bid = blockIdx.x;
    int rmod = bid % 10;
    int tid = threadIdx.x;

    if (rmod != 9) {
        // ---------------- k0 path: transpose with fused JX/JY ----------------
        int k0id = (bid/10)*9 + rmod;            // 0 .. 9215
        int bx = k0id % 12, by = (k0id/12) % 96, bz = k0id / (12*96);
        int ct = bx / 3, yt = bx % 3;
        int xx = by, b = bz;
        int tx = tid & 31, ty = tid >> 5;
        #pragma unroll
        for (int rr = ty; rr < 32; rr += 8) {
            int c = ct*32 + rr;
            int y = yt*32 + tx;
            int src = ((b*CIN + c)*HH + xx)*WIW + y;
            sm.a.tI [rr][tx] = I [src];
            sm.a.tIX[rr][tx] = IX[src];
            sm.a.tIY[rr][tx] = IY[src];
            sm.a.tIT[rr][tx] = IT[src];
        }
        __syncthreads();
        #pragma unroll
        for (int rr = ty; rr < 32; rr += 8) {
            int c = ct*32 + tx;
            int y = yt*32 + rr;
            int dst = ((b*HH + xx)*WIW + y)*CIN + c;
            float vi = sm.a.tI[tx][rr];
            g_TI [dst] = vi;
            g_TIT[dst] = sm.a.tIT[tx][rr];
            g_TJX[dst] = sm.a.tIX[tx][rr] - 0.5f*vi;
            g_TJY[dst] = sm.a.tIY[tx][rr] - 0.5f*vi;
        }
        return;
    }

    // ---------------- k1 path: logits + rect splits + softmax ----------------
    int p0 = (bid/10) * K1_PTS;

    for (int i = tid; i < K1_PTS*CC; i += 256) {
        int p = i >> 9, k = i & 511;
        sm.b.xs[p][k] = x[(p0+p)*CC + k];
    }
    __syncthreads();

    // mask logits: thread = (point, 4 cols); float4 loads; split-4 accumulation
    {
        int p = tid >> 4, q = tid & 15;
        float4 a0 = {0,0,0,0}, a1 = {0,0,0,0}, a2 = {0,0,0,0}, a3 = {0,0,0,0};
        #pragma unroll 4
        for (int k = 0; k < CC; k += 4) {
            float4 xv = *(const float4*)&sm.b.xs[p][k];
            float4 w0 = *(const float4*)&Wm[(k+0)*64 + q*4];
            float4 w1 = *(const float4*)&Wm[(k+1)*64 + q*4];
            float4 w2 = *(const float4*)&Wm[(k+2)*64 + q*4];
            float4 w3 = *(const float4*)&Wm[(k+3)*64 + q*4];
            a0.x += xv.x*w0.x; a0.y += xv.x*w0.y; a0.z += xv.x*w0.z; a0.w += xv.x*w0.w;
            a1.x += xv.y*w1.x; a1.y += xv.y*w1.y; a1.z += xv.y*w1.z; a1.w += xv.y*w1.w;
            a2.x += xv.z*w2.x; a2.y += xv.z*w2.y; a2.z += xv.z*w2.z; a2.w += xv.z*w2.w;
            a3.x += xv.w*w3.x; a3.y += xv.w*w3.y; a3.z += xv.w*w3.z; a3.w += xv.w*w3.w;
        }
        sm.b.lg[p][7 + q*4 + 0] = (a0.x+a1.x) + (a2.x+a3.x);
        sm.b.lg[p][7 + q*4 + 1] = (a0.y+a1.y) + (a2.y+a3.y);
        sm.b.lg[p][7 + q*4 + 2] = (a0.z+a1.z) + (a2.z+a3.z);
        sm.b.lg[p][7 + q*4 + 3] = (a0.w+a1.w) + (a2.w+a3.w);
    }

    // ratio logits: pairwise fp32 chunks of 8, summed into double
    if (tid < K1_PTS*7) {
        int p = tid / 7, j = tid % 7;
        double acc = 0.0;
        #pragma unroll 4
        for (int kb = 0; kb < CC; kb += 16) {
            const float* xp = sm.b.xs[p];
            float s0 = ((xp[kb+0]*Wr[(kb+0)*7+j] + xp[kb+1]*Wr[(kb+1)*7+j])
                      + (xp[kb+2]*Wr[(kb+2)*7+j] + xp[kb+3]*Wr[(kb+3)*7+j]))
                     + ((xp[kb+4]*Wr[(kb+4)*7+j] + xp[kb+5]*Wr[(kb+5)*7+j])
                      + (xp[kb+6]*Wr[(kb+6)*7+j] + xp[kb+7]*Wr[(kb+7)*7+j]));
            float s1 = ((xp[kb+8]*Wr[(kb+8)*7+j] + xp[kb+9]*Wr[(kb+9)*7+j])
                      + (xp[kb+10]*Wr[(kb+10)*7+j] + xp[kb+11]*Wr[(kb+11)*7+j]))
                     + ((xp[kb+12]*Wr[(kb+12)*7+j] + xp[kb+13]*Wr[(kb+13)*7+j])
                      + (xp[kb+14]*Wr[(kb+14)*7+j] + xp[kb+15]*Wr[(kb+15)*7+j]));
            acc += (double)s0 + (double)s1;
        }
        sm.b.lg[p][j] = (float)acc;
    }
    __syncthreads();

    // rect splits: one thread per point (fp32, matching reference formula)
    if (tid < K1_PTS) {
        int gp = p0 + tid;
        float rat[7];
        #pragma unroll
        for (int i = 0; i < 7; i++)
            rat[i] = 1.f / (1.f + expf(-(sm.b.lg[tid][i] + br[i])));
        float R0[4];
        #pragma unroll
        for (int i = 0; i < 4; i++) R0[i] = r[gp*4 + i];

        float A[2][4], Bv[4][4], Cv[8][4];
        {
            float mid = R0[0]*(1.f-rat[0]) + R0[2]*rat[0];
            A[0][0]=R0[0]; A[0][1]=R0[1]; A[0][2]=mid;   A[0][3]=R0[3];
            A[1][0]=mid;   A[1][1]=R0[1]; A[1][2]=R0[2]; A[1][3]=R0[3];
        }
        #pragma unroll
        for (int k = 0; k < 2; k++) {
            float rt  = rat[1+k];
            float mid = A[k][1]*(1.f-rt) + A[k][3]*rt;
            Bv[k][0]=A[k][0];   Bv[k][1]=A[k][1]; Bv[k][2]=A[k][2];   Bv[k][3]=mid;
            Bv[2+k][0]=A[k][0]; Bv[2+k][1]=mid;   Bv[2+k][2]=A[k][2]; Bv[2+k][3]=A[k][3];
        }
        #pragma unroll
        for (int k = 0; k < 4; k++) {
            float rt  = rat[3+k];
            float mid = Bv[k][0]*(1.f-rt) + Bv[k][2]*rt;
            Cv[k][0]=Bv[k][0]; Cv[k][1]=Bv[k][1]; Cv[k][2]=mid;      Cv[k][3]=Bv[k][3];
            Cv[4+k][0]=mid;    Cv[4+k][1]=Bv[k][1]; Cv[4+k][2]=Bv[k][2]; Cv[4+k][3]=Bv[k][3];
        }
        #pragma unroll
        for (int i = 0; i < 8;  i++) sm.b.rects[tid][i]    = A[i>>2][i&3];
        #pragma unroll
        for (int i = 0; i < 16; i++) sm.b.rects[tid][8+i]  = Bv[i>>2][i&3];
        #pragma unroll
        for (int i = 0; i < 32; i++) sm.b.rects[tid][24+i] = Cv[i>>2][i&3];
    }
    __syncthreads();

    // softmax over rects per (point, group)
    if (tid < K1_PTS*8) {
        int p = tid >> 3, g = tid & 7;
        float m[8], mx = -1e30f;
        #pragma unroll
        for (int s = 0; s < 8; s++) { m[s] = sm.b.lg[p][7 + s*8 + g] + bm[s*8 + g]; mx = fmaxf(mx, m[s]); }
        float sum = 0.f;
        #pragma unroll
        for (int s = 0; s < 8; s++) { m[s] = expf(m[s]-mx); sum += m[s]; }
        float inv = 1.f / sum;
        #pragma unroll
        for (int s = 0; s < 8; s++) g_mask[(p0+p)*64 + s*8 + g] = m[s]*inv;
    }

    for (int i = tid; i < K1_PTS*8;  i += 256) out[L0OFF + p0*8  + i] = sm.b.rects[i>>3][i&7];
    for (int i = tid; i < K1_PTS*16; i += 256) out[L1OFF + p0*16 + i] = sm.b.rects[i>>4][8  + (i&15)];
    for (int i = tid; i < K1_PTS*32; i += 256) out[L2OFF + p0*32 + i] = sm.b.rects[i>>5][24 + (i&31)];
}

// ============================================================================
// K2: integral-image sampling, 18-corner dedup, edge terms dropped (exact
//     cancellation), scatter-add into Sraw. float4 channels: 1 warp per point,
//     4 points per 128-thread block. 162 LDG.128 per warp per point.
// ============================================================================
__global__ void __launch_bounds__(128) k2_sample(const float* __restrict__ out) {
    __shared__ float rrs[4][32];
    __shared__ float msk[4][64];
    __shared__ int   sxX[4][7], sxXm[4][7], syY[4][4], syYm[4][4];
    __shared__ float swx1[4][7], swx2[4][7], swy1[4][4], swy2[4][4];
    int tid = threadIdx.x;
    int w = tid >> 5, l = tid & 31;          // warp = point, lane = channel/4
    int pt = blockIdx.x*4 + w;

    rrs[w][l]     = out[L2OFF + pt*32 + l] * 95.f;
    msk[w][l]     = g_mask[pt*64 + l];
    msk[w][l+32]  = g_mask[pt*64 + 32 + l];
    __syncwarp();
    if (l < 7) {
        const int xsrc[7] = {0, 4, 22, 2, 6, 10, 14};
        float px = rrs[w][xsrc[l]];
        float Xf = ceilf(px);
        int X = (int)Xf, Xm = max(X-1, 0);
        float dx = Xf - px;
        float w1 = 0.5f*dx*dx;
        swx1[w][l] = w1; swx2[w][l] = dx - w1;
        sxX[w][l]  = X *(WIW*32);            // float4 units
        sxXm[w][l] = Xm*(WIW*32);
    } else if (l >= 8 && l < 12) {
        const int ysrc[4] = {1, 3, 7, 11};
        int t = l - 8;
        float py = rrs[w][ysrc[t]];
        float Yf = ceilf(py);
        int Y = (int)Yf, Ym = max(Y-1, 0);
        float dy = Yf - py;
        float w1 = 0.5f*dy*dy;
        swy1[w][t] = w1; swy2[w][t] = dy - w1;
        syY[w][t]  = Y *32;                  // float4 units
        syYm[w][t] = Ym*32;
    }
    __syncwarp();

    const float4* TI4  = (const float4*)g_TI;
    const float4* TIT4 = (const float4*)g_TIT;
    const float4* TJX4 = (const float4*)g_TJX;
    const float4* TJY4 = (const float4*)g_TJY;
    int b = pt >> 11;
    int base4 = b*(HH*WIW*32) + l;           // float4 units; channels 4l..4l+3

    // corner tables + per-corner scatter targets/signs (corner feeds <=2 rects)
    const int   CXI[18] = {0,0,1,1,3,3, 1,2,2,4,4, 0,1,5,5, 2,6,6};
    const int   CYI[18] = {0,1,0,1,0,1, 2,0,2,0,2, 3,3,1,3, 3,2,3};
    const int   U0 [18] = {0,0,1,4,0,0, 1,5,5,1,1, 2,6,2,2, 7,3,3};
    const float G0 [18] = {+1.f,-1.f,+1.f,+1.f,-1.f,+1.f, -1.f,-1.f,+1.f,-1.f,+1.f,
                           -1.f,+1.f,-1.f,+1.f, +1.f,-1.f,+1.f};
    const int   U1 [18] = {0,2,4,6,4,4, 3,0,7,5,5, 0,3,6,6, 0,7,7};
    const float G1 [18] = {0.f,+1.f,-1.f,-1.f,+1.f,-1.f, +1.f,0.f,-1.f,+1.f,-1.f,
                           0.f,-1.f,+1.f,-1.f, 0.f,+1.f,-1.f};

    float4 Sraw[8];
    #pragma unroll
    for (int s = 0; s < 8; s++) Sraw[s] = make_float4(0.f,0.f,0.f,0.f);

    #pragma unroll
    for (int i = 0; i < 18; i++) {
        int xi = CXI[i], yi = CYI[i];
        int oX = sxX[w][xi], oXm = sxXm[w][xi];
        int oY = syY[w][yi], oYm = syYm[w][yi];
        float wx1 = swx1[w][xi], wx2 = swx2[w][xi];
        float wy1 = swy1[w][yi], wy2 = swy2[w][yi];
        int aXY   = base4 + oX  + oY;
        int aXYm  = base4 + oX  + oYm;
        int aXmY  = base4 + oXm + oY;
        int aXmYm = base4 + oXm + oYm;
        float4 tit  = TIT4[aXY];
        float4 jxm  = TJX4[aXYm], jx0 = TJX4[aXY];
        float4 jym  = TJY4[aXmY], jy0 = TJY4[aXY];
        float4 timm = TI4[aXmYm], tim0 = TI4[aXmY];
        float4 ti0m = TI4[aXYm],  ti00 = TI4[aXY];
        float4 v;
        v.x = tit.x - (wy1*jxm.x + wy2*jx0.x) - (wx1*jym.x + wx2*jy0.x)
            + (wx1*(wy1*timm.x + wy2*tim0.x) + wx2*(wy1*ti0m.x + wy2*ti00.x));
        v.y = tit.y - (wy1*jxm.y + wy2*jx0.y) - (wx1*jym.y + wx2*jy0.y)
            + (wx1*(wy1*timm.y + wy2*tim0.y) + wx2*(wy1*ti0m.y + wy2*ti00.y));
        v.z = tit.z - (wy1*jxm.z + wy2*jx0.z) - (wx1*jym.z + wx2*jy0.z)
            + (wx1*(wy1*timm.z + wy2*tim0.z) + wx2*(wy1*ti0m.z + wy2*ti00.z));
        v.w = tit.w - (wy1*jxm.w + wy2*jx0.w) - (wx1*jym.w + wx2*jy0.w)
            + (wx1*(wy1*timm.w + wy2*tim0.w) + wx2*(wy1*ti0m.w + wy2*ti00.w));
        float g0 = G0[i], g1 = G1[i];
        int u0 = U0[i], u1 = U1[i];
        Sraw[u0].x += g0*v.x; Sraw[u0].y += g0*v.y; Sraw[u0].z += g0*v.z; Sraw[u0].w += g0*v.w;
        Sraw[u1].x += g1*v.x; Sraw[u1].y += g1*v.y; Sraw[u1].z += g1*v.z; Sraw[u1].w += g1*v.w;
    }

    // mask-weighted combine
    float4 zacc[8];
    #pragma unroll
    for (int g = 0; g < 8; g++) zacc[g] = make_float4(0.f,0.f,0.f,0.f);
    #pragma unroll
    for (int s = 0; s < 8; s++) {
        float x1 = rrs[w][s*4+0], y1 = rrs[w][s*4+1];
        float x2 = rrs[w][s*4+2], y2 = rrs[w][s*4+3];
        float inva = 1.f / (fabsf((x1-x2)*(y1-y2)) + 1e-9f);
        float4 Sv;
        Sv.x = Sraw[s].x * inva; Sv.y = Sraw[s].y * inva;
        Sv.z = Sraw[s].z * inva; Sv.w = Sraw[s].w * inva;
        #pragma unroll
        for (int g = 0; g < 8; g++) {
            float m = msk[w][s*8+g];
            zacc[g].x += m*Sv.x; zacc[g].y += m*Sv.y;
            zacc[g].z += m*Sv.z; zacc[g].w += m*Sv.w;
        }
    }
    float4* gZ4 = (float4*)g_Z;
    #pragma unroll
    for (int g = 0; g < 8; g++)
        gZ4[(pt*8 + g)*32 + l] = zacc[g];
}

// ============================================================================
// K3: per-group GEMM, 64 pts x 64 cols per block, 256 threads, 4x4 per thread
//     (R10-measured 67.8us configuration: Zs transposed [kk][p], pad 68)
// ============================================================================
__global__ void k3_gemm(const float* __restrict__ Wsamp, const float* __restrict__ bsamp,
                        float* __restrict__ out) {
    __shared__ float Zs[64][68];
    __shared__ float Wt[64][68];
    int p0  = blockIdx.x * 64;
    int g   = blockIdx.y;
    int tid = threadIdx.x;
    int tx  = tid & 15, ty = tid >> 4;
    float acc[4][4] = {};
    for (int kb = 0; kb < CIN; kb += 64) {
        __syncthreads();
        for (int i = tid; i < 4096; i += 256) {
            int p = i >> 6, kk = i & 63;
            Zs[kk][p] = g_Z[((p0+p)*8 + g)*CIN + kb + kk];
        }
        for (int i = tid; i < 4096; i += 256) {
            int kk = i >> 6, cc = i & 63;
            Wt[kk][cc] = Wsamp[(kb+kk)*CC + g*64 + cc];
        }
        __syncthreads();
        #pragma unroll 8
        for (int kk = 0; kk < 64; kk++) {
            float4 av = *(const float4*)&Zs[kk][ty*4];
            float4 bv = *(const float4*)&Wt[kk][tx*4];
            acc[0][0] += av.x*bv.x; acc[0][1] += av.x*bv.y; acc[0][2] += av.x*bv.z; acc[0][3] += av.x*bv.w;
            acc[1][0] += av.y*bv.x; acc[1][1] += av.y*bv.y; acc[1][2] += av.y*bv.z; acc[1][3] += av.y*bv.w;
            acc[2][0] += av.z*bv.x; acc[2][1] += av.z*bv.y; acc[2][2] += av.z*bv.z; acc[2][3] += av.z*bv.w;
            acc[3][0] += av.w*bv.x; acc[3][1] += av.w*bv.y; acc[3][2] += av.w*bv.z; acc[3][3] += av.w*bv.w;
        }
    }
    int c0 = g*64 + tx*4;
    float4 bb = *(const float4*)&bsamp[c0];
    #pragma unroll
    for (int i = 0; i < 4; i++) {
        int row = p0 + ty*4 + i;
        float4 o;
        o.x = acc[i][0] + bb.x; o.y = acc[i][1] + bb.y;
        o.z = acc[i][2] + bb.z; o.w = acc[i][3] + bb.w;
        *(float4*)&out[row*CC + c0] = o;
    }
}

// ============================================================================
// K4: LayerNorm + residual, in place. Two-pass variance; float4 I/O.
// ============================================================================
__global__ void k4_ln(const float* __restrict__ x, const float* __restrict__ lng,
                      const float* __restrict__ lnb, float* __restrict__ out) {
    __shared__ float red[4];
    int pt = blockIdx.x, tid = threadIdx.x;
    int c = tid*4;
    float4 v = *(const float4*)&out[pt*CC + c];
    float s1 = (v.x+v.y) + (v.z+v.w);
    #pragma unroll
    for (int o = 16; o; o >>= 1) s1 += __shfl_xor_sync(0xFFFFFFFFu, s1, o);
    if ((tid & 31) == 0) red[tid>>5] = s1;
    __syncthreads();
    float mu = (red[0]+red[1]+red[2]+red[3]) * (1.f/512.f);
    __syncthreads();

    float d0 = v.x-mu, d1 = v.y-mu, d2 = v.z-mu, d3 = v.w-mu;
    float s2 = (d0*d0+d1*d1) + (d2*d2+d3*d3);
    #pragma unroll
    for (int o = 16; o; o >>= 1) s2 += __shfl_xor_sync(0xFFFFFFFFu, s2, o);
    if ((tid & 31) == 0) red[tid>>5] = s2;
    __syncthreads();
    float var = (red[0]+red[1]+red[2]+red[3]) * (1.f/512.f);
    float rs  = rsqrtf(var + 1e-5f);

    float4 gv = *(const float4*)&lng[c];
    float4 bv = *(const float4*)&lnb[c];
    float4 xv = *(const float4*)&x[pt*CC + c];
    float4 o;
    o.x = d0*rs*gv.x + bv.x + xv.x;
    o.y = d1*rs*gv.y + bv.y + xv.y;
    o.z = d2*rs*gv.z + bv.z + xv.z;
    o.w = d3*rs*gv.w + bv.w + xv.w;
    *(float4*)&out[pt*CC + c] = o;
}

// ============================================================================
extern "C" void kernel_launch(void* const* d_in, const int* in_sizes, int n_in,
                              void* d_out, int out_size) {
    const float* x  = (const float*)d_in[0];
    const float* r  = (const float*)d_in[1];
    const float* I  = (const float*)d_in[2];
    const float* IX = (const float*)d_in[3];
    const float* IY = (const float*)d_in[4];
    const float* IT = (const float*)d_in[5];
    const float* Wr = (const float*)d_in[6];
    const float* br = (const float*)d_in[7];
    const float* Wm = (const float*)d_in[8];
    const float* bm = (const float*)d_in[9];
    const float* Ws = (const float*)d_in[10];
    const float* bs = (const float*)d_in[11];
    const float* lg = (const float*)d_in[12];
    const float* lb = (const float*)d_in[13];
    float* out = (float*)d_out;

    k01_fused<<<K01_BLOCKS, 256>>>(I, IX, IY, IT, x, r, Wr, br, Wm, bm, out);
    k2_sample<<<NPTS/4, 128>>>(out);
    k3_gemm<<<dim3(NPTS/64, 8), 256>>>(Ws, bs, out);
    k4_ln<<<NPTS, 128>>>(x, lg, lb, out);
}